// round 14
// baseline (speedup 1.0000x reference)
#include <cuda_runtime.h>
#include <math.h>

// Problem dims
#define Hd   448
#define Wd   224
#define Dd   12
#define Cd   10
#define HW   100352          // 448*224
#define DHW  1204224         // 12*HW
#define CDHW 12042240        // 10*DHW
#define INV_HW (1.0f/100352.0f)
#define NB_EW 1024           // blocks for init
#define NB_Q  672            // blocks for K3 (D*H/8)
#define NB_F  1024           // blocks for final
#define PI_D 3.14159265358979323846
#define TSTR8 9              // padded tile stride (float2) for K2 (8-col tiles)

// -------- device scratch (static __device__ arrays: allocation-free) --------
__device__ float2 g_scr[CDHW];     // coil-expanded k-rows, w PERMUTED
__device__ float2 g_p2[2][DHW];    // double-buffered CG direction p
__device__ float2 g_r2[2][DHW];    // double-buffered residual r
__device__ float2 g_b[DHW];
__device__ float2 g_q[DHW];
__device__ float2 g_W224[224];
__device__ float2 g_W448[448];
__device__ float  g_maskf[HW];     // permuted mask * INV_HW, layout [w][km][k1][s]
__device__ float2 g_qp_part[NB_Q];
__device__ float2 g_rq_part[NB_Q];
__device__ float  g_qq_part[NB_Q];
__device__ float  g_rrp[NB_EW];    // ||r0||^2 partials (from k_init)
__device__ float  g_rr[8];         // rr chain
__device__ float2 g_al[8];
__device__ float  g_be[8];

// -------- complex helpers --------
__device__ __forceinline__ float2 cmulf(float2 a, float2 b) {
    return make_float2(a.x*b.x - a.y*b.y, a.x*b.y + a.y*b.x);
}
__device__ __forceinline__ void cmadd(float2& acc, float2 a, float2 b) {
    acc.x = fmaf(a.x, b.x, fmaf(-a.y, b.y, acc.x));
    acc.y = fmaf(a.x, b.y, fmaf( a.y, b.x, acc.y));
}
__device__ __forceinline__ float2 cadd(float2 a, float2 b){ return make_float2(a.x+b.x, a.y+b.y); }
__device__ __forceinline__ float2 csub(float2 a, float2 b){ return make_float2(a.x-b.x, a.y-b.y); }

__device__ __forceinline__ int bitrev5(int t) {
    return ((t & 1) << 4) | ((t & 2) << 2) | (t & 4) | ((t & 8) >> 2) | ((t & 16) >> 4);
}

// -------- symmetric DFT-7 --------
template<bool INV>
__device__ __forceinline__ void dft7(const float2 x[7], float2 X[7]) {
    const float C1f =  0.62348980185873359f;
    const float C2f = -0.22252093395631440f;
    const float C3f = -0.90096886790241915f;
    const float S1f =  0.78183148246802981f;
    const float S2f =  0.97492791218182360f;
    const float S3f =  0.43388373911755812f;
    float2 a1 = cadd(x[1], x[6]), b1 = csub(x[1], x[6]);
    float2 a2 = cadd(x[2], x[5]), b2 = csub(x[2], x[5]);
    float2 a3 = cadd(x[3], x[4]), b3 = csub(x[3], x[4]);
    X[0] = make_float2(x[0].x + a1.x + a2.x + a3.x,
                       x[0].y + a1.y + a2.y + a3.y);
    float2 u1, u2, u3, v1, v2, v3;
    u1.x = fmaf(C1f,a1.x, fmaf(C2f,a2.x, fmaf(C3f,a3.x, x[0].x)));
    u1.y = fmaf(C1f,a1.y, fmaf(C2f,a2.y, fmaf(C3f,a3.y, x[0].y)));
    u2.x = fmaf(C2f,a1.x, fmaf(C3f,a2.x, fmaf(C1f,a3.x, x[0].x)));
    u2.y = fmaf(C2f,a1.y, fmaf(C3f,a2.y, fmaf(C1f,a3.y, x[0].y)));
    u3.x = fmaf(C3f,a1.x, fmaf(C1f,a2.x, fmaf(C2f,a3.x, x[0].x)));
    u3.y = fmaf(C3f,a1.y, fmaf(C1f,a2.y, fmaf(C2f,a3.y, x[0].y)));
    v1.x = fmaf(S1f,b1.x, fmaf( S2f,b2.x,  S3f*b3.x));
    v1.y = fmaf(S1f,b1.y, fmaf( S2f,b2.y,  S3f*b3.y));
    v2.x = fmaf(S2f,b1.x, fmaf(-S3f,b2.x, -S1f*b3.x));
    v2.y = fmaf(S2f,b1.y, fmaf(-S3f,b2.y, -S1f*b3.y));
    v3.x = fmaf(S3f,b1.x, fmaf(-S1f,b2.x,  S2f*b3.x));
    v3.y = fmaf(S3f,b1.y, fmaf(-S1f,b2.y,  S2f*b3.y));
    if (!INV) {
        X[1] = make_float2(u1.x + v1.y, u1.y - v1.x);
        X[6] = make_float2(u1.x - v1.y, u1.y + v1.x);
        X[2] = make_float2(u2.x + v2.y, u2.y - v2.x);
        X[5] = make_float2(u2.x - v2.y, u2.y + v2.x);
        X[3] = make_float2(u3.x + v3.y, u3.y - v3.x);
        X[4] = make_float2(u3.x - v3.y, u3.y + v3.x);
    } else {
        X[1] = make_float2(u1.x - v1.y, u1.y + v1.x);
        X[6] = make_float2(u1.x + v1.y, u1.y - v1.x);
        X[2] = make_float2(u2.x - v2.y, u2.y + v2.x);
        X[5] = make_float2(u2.x + v2.y, u2.y - v2.x);
        X[3] = make_float2(u3.x - v3.y, u3.y + v3.x);
        X[4] = make_float2(u3.x + v3.y, u3.y - v3.x);
    }
}

__device__ __forceinline__ void bfly(float2& v, int t, int m, float2 tw) {
    float2 o;
    o.x = __shfl_xor_sync(0xffffffffu, v.x, m);
    o.y = __shfl_xor_sync(0xffffffffu, v.y, m);
    float2 sum = make_float2(v.x + o.x, v.y + o.y);
    float2 dif = make_float2(o.x - v.x, o.y - v.y);
    float2 dm  = cmulf(dif, tw);
    v = (t & m) ? dm : sum;
}
__device__ __forceinline__ void ibfly(float2& v, int t, int m, float2 tw) {
    float2 twc = make_float2(tw.x, -tw.y);
    float2 vv = v;
    if (t & m) vv = cmulf(v, twc);
    float2 o;
    o.x = __shfl_xor_sync(0xffffffffu, vv.x, m);
    o.y = __shfl_xor_sync(0xffffffffu, vv.y, m);
    v = (t & m) ? csub(o, vv) : cadd(vv, o);
}

// -------- deterministic block reductions --------
__device__ __forceinline__ float blockReduceF(float v) {
    __shared__ float red[8];
    int lane = threadIdx.x & 31, wp = threadIdx.x >> 5;
    #pragma unroll
    for (int o = 16; o > 0; o >>= 1) v += __shfl_down_sync(0xffffffffu, v, o);
    if (lane == 0) red[wp] = v;
    __syncthreads();
    if (wp == 0) {
        v = (lane < 8) ? red[lane] : 0.f;
        #pragma unroll
        for (int o = 4; o > 0; o >>= 1) v += __shfl_down_sync(0xffffffffu, v, o);
    }
    __syncthreads();
    return v;
}
__device__ __forceinline__ float2 blockReduceC(float2 v) {
    __shared__ float2 redc[8];
    int lane = threadIdx.x & 31, wp = threadIdx.x >> 5;
    #pragma unroll
    for (int o = 16; o > 0; o >>= 1) {
        v.x += __shfl_down_sync(0xffffffffu, v.x, o);
        v.y += __shfl_down_sync(0xffffffffu, v.y, o);
    }
    if (lane == 0) redc[wp] = v;
    __syncthreads();
    if (wp == 0) {
        v = (lane < 8) ? redc[lane] : make_float2(0.f, 0.f);
        #pragma unroll
        for (int o = 4; o > 0; o >>= 1) {
            v.x += __shfl_down_sync(0xffffffffu, v.x, o);
            v.y += __shfl_down_sync(0xffffffffu, v.y, o);
        }
    }
    __syncthreads();
    return v;
}

// -------- setup: twiddles + permuted mask table --------
__global__ void k_setup(const int* __restrict__ mask) {
    int idx = blockIdx.x * 256 + threadIdx.x;
    if (idx < 224) {
        double a = -2.0 * PI_D * (double)idx / 224.0;
        g_W224[idx] = make_float2((float)cos(a), (float)sin(a));
    }
    if (idx < 448) {
        double a = -2.0 * PI_D * (double)idx / 448.0;
        g_W448[idx] = make_float2((float)cos(a), (float)sin(a));
    }
    if (idx < HW) {
        int s = idx & 31;
        int rest = idx >> 5;
        int k1 = rest % 7;
        int q = rest / 7;
        int km = q & 1;
        int j = q >> 1;
        int t = j & 31, k1w = j >> 5;
        int wt = 7 * bitrev5(t) + k1w;
        int ktrue = 7 * (2 * bitrev5(s) + km) + k1;
        g_maskf[idx] = mask[ktrue * Wd + wt] ? INV_HW : 0.f;
    }
}

// -------- forward 224-pt FFT per warp --------
__device__ __forceinline__ void fft224_fwd(const float2* sW, int t,
        float2 tw16, float2 tw8, float2 tw4, float2 tw2,
        const float2 a[7], float2 out[7]) {
    float2 y[7];
    dft7<false>(a, y);
    float2 wstep = sW[t];
    float2 cur = make_float2(1.f, 0.f);
    #pragma unroll
    for (int k1 = 0; k1 < 7; k1++) {
        float2 v = cmulf(y[k1], cur);
        cur = cmulf(cur, wstep);
        bfly(v, t, 16, tw16);
        bfly(v, t,  8, tw8);
        bfly(v, t,  4, tw4);
        bfly(v, t,  2, tw2);
        float2 o;
        o.x = __shfl_xor_sync(0xffffffffu, v.x, 1);
        o.y = __shfl_xor_sync(0xffffffffu, v.y, 1);
        v = (t & 1) ? make_float2(o.x - v.x, o.y - v.y)
                    : make_float2(v.x + o.x, v.y + o.y);
        out[k1] = v;
    }
}

// -------- inverse 224-pt FFT per warp (permuted input) --------
__device__ __forceinline__ void fft224_inv(const float2* sW, int t,
        float2 tw16, float2 tw8, float2 tw4, float2 tw2,
        float2 y[7], float2 xo[7]) {
    float2 wstep = sW[t]; wstep.y = -wstep.y;
    float2 cur = make_float2(1.f, 0.f);
    #pragma unroll
    for (int k1 = 0; k1 < 7; k1++) {
        float2 v = y[k1];
        float2 o;
        o.x = __shfl_xor_sync(0xffffffffu, v.x, 1);
        o.y = __shfl_xor_sync(0xffffffffu, v.y, 1);
        v = (t & 1) ? csub(o, v) : cadd(v, o);
        ibfly(v, t,  2, tw2);
        ibfly(v, t,  4, tw4);
        ibfly(v, t,  8, tw8);
        ibfly(v, t, 16, tw16);
        y[k1] = cmulf(v, cur);
        cur = cmulf(cur, wstep);
    }
    dft7<true>(y, xo);
}

// -------- K0: p0 = s*(zf + mu*z); r0 = p0; b = 0; partial ||r0||^2 --------
__global__ __launch_bounds__(256) void k_init(const float* __restrict__ z,
                                              const float* __restrict__ zf,
                                              const float* __restrict__ miu) {
    float mu = fabsf(miu[0]);
    float rr = 0.f;
    for (int n = blockIdx.x * 256 + threadIdx.x; n < DHW; n += NB_EW * 256) {
        int w = n % Wd;
        int h = (n / Wd) % Hd;
        float s = ((h + w) & 1) ? -1.f : 1.f;
        float pr = s * (zf[n] + mu * z[n]);
        float pi = s * (zf[DHW + n] + mu * z[DHW + n]);
        float2 p = make_float2(pr, pi);
        g_p2[0][n] = p; g_r2[0][n] = p; g_b[n] = make_float2(0.f, 0.f);
        rr = fmaf(pr, pr, fmaf(pi, pi, rr));
    }
    rr = blockReduceF(rr);
    if (threadIdx.x == 0) g_rrp[blockIdx.x] = rr;
}

// -------- k_scalar: reduce partials -> al(it), rr(it+1), be(it) --------
__global__ void k_scalar(int it) {
    int tid = threadIdx.x;
    float2 qp = make_float2(0.f, 0.f), rq = make_float2(0.f, 0.f);
    float qq = 0.f;
    for (int i = tid; i < NB_Q; i += 256) {
        qp.x += g_qp_part[i].x; qp.y += g_qp_part[i].y;
        rq.x += g_rq_part[i].x; rq.y += g_rq_part[i].y;
        qq += g_qq_part[i];
    }
    qp = blockReduceC(qp);
    rq = blockReduceC(rq);
    qq = blockReduceF(qq);
    float rr0 = 0.f;
    if (it == 0) {
        float v = 0.f;
        for (int i = tid; i < NB_EW; i += 256) v += g_rrp[i];
        rr0 = blockReduceF(v);
    }
    if (tid == 0) {
        float rrv = (it == 0) ? rr0 : g_rr[it];
        if (it == 0) g_rr[0] = rr0;
        float den = qp.x * qp.x + qp.y * qp.y;
        float2 al = make_float2(rrv * qp.x / den, -rrv * qp.y / den);
        g_al[it] = al;
        float rr_new = rrv - 2.f * (al.x * rq.x + al.y * rq.y)
                     + (al.x * al.x + al.y * al.y) * qq;
        g_rr[it + 1] = rr_new;
        g_be[it] = rr_new / rrv;
    }
}

// -------- K1: fused CG update (it>0) + forward row FFTs with coil expand --------
// it>0: p_new = (r_old - al*q) + be*p_old computed in-register by every block;
// c==0 blocks persist b += al*p_old, r_new, p_new. Buffers: read (it-1)&1, write it&1.
__global__ __launch_bounds__(256) void k_rowfft_fwd(const float* __restrict__ cr,
                                                    const float* __restrict__ ci,
                                                    int it) {
    __shared__ float2 sW[224];
    __shared__ float2 s_al;
    __shared__ float  s_be;
    int tid = threadIdx.x;
    for (int i = tid; i < 224; i += 256) sW[i] = g_W224[i];
    if (it > 0 && tid == 0) { s_al = g_al[it - 1]; s_be = g_be[it - 1]; }
    __syncthreads();
    float2 al = make_float2(0.f, 0.f);
    float be = 0.f;
    if (it > 0) { al = s_al; be = s_be; }
    int warp = tid >> 5, t = tid & 31;
    float2 tw16 = sW[7  * (t & 15)];
    float2 tw8  = sW[14 * (t & 7)];
    float2 tw4  = sW[28 * (t & 3)];
    float2 tw2  = sW[56 * (t & 1)];
    int rid = blockIdx.x * 8 + warp;                 // < 53760
    int c = rid / (Dd * Hd);
    int r2 = rid - c * (Dd * Hd);
    int h = r2 % Hd;
    int src = (it > 0) ? ((it - 1) & 1) : 0;
    const float2* pin  = g_p2[src] + r2 * Wd;
    float2* pout = g_p2[it & 1] + r2 * Wd;
    const float2* rin  = g_r2[src] + r2 * Wd;
    float2* rout = g_r2[it & 1] + r2 * Wd;
    const float2* qrow = g_q + r2 * Wd;
    float2* brow = g_b + r2 * Wd;
    const float* crr = cr + (c * Hd + h) * Wd;
    const float* cii = ci + (c * Hd + h) * Wd;
    float2 a[7];
    #pragma unroll
    for (int n1 = 0; n1 < 7; n1++) {
        int idx = n1 * 32 + t;
        float2 p = pin[idx];
        if (it > 0) {
            float2 q = qrow[idx];
            float2 rv = rin[idx];
            float rnx = rv.x - (al.x * q.x - al.y * q.y);
            float rny = rv.y - (al.x * q.y + al.y * q.x);
            float2 pn = make_float2(fmaf(be, p.x, rnx), fmaf(be, p.y, rny));
            if (c == 0) {
                float2 b = brow[idx];
                b.x += al.x * p.x - al.y * p.y;
                b.y += al.x * p.y + al.y * p.x;
                brow[idx] = b;
                rout[idx] = make_float2(rnx, rny);
                pout[idx] = pn;
            }
            p = pn;
        }
        float2 co = make_float2(crr[idx], cii[idx]);
        a[n1] = cmulf(p, co);
    }
    float2 out[7];
    fft224_fwd(sW, t, tw16, tw8, tw4, tw2, a, out);
    float2* orow = g_scr + (size_t)rid * Wd;
    #pragma unroll
    for (int k1 = 0; k1 < 7; k1++) orow[k1 * 32 + t] = out[k1];   // permuted, coalesced
}

// -------- K2: warp-per-column 448-pt FFT + mask + IFFT, 8-column tiles --------
__global__ void __launch_bounds__(256, 3) k_colfft() {
    extern __shared__ float2 sh[];                   // tile[448*TSTR8] ++ W448[448]
    float2* tile = sh;
    float2* sW = sh + 448 * TSTR8;
    int tid = threadIdx.x;
    for (int i = tid; i < 448; i += 256) sW[i] = g_W448[i];
    int wt = blockIdx.x % 28;
    int cd = blockIdx.x / 28;
    int w0 = wt * 8;
    float2* gbase = g_scr + (size_t)cd * HW;
    int lg = tid & 7, ls = tid >> 3;
    int g = tid >> 5, s = tid & 31;
    for (int i = 0; i < 14; i++) {
        int h = ls + 32 * i;
        tile[h * TSTR8 + lg] = gbase[h * Wd + w0 + lg];
    }
    __syncthreads();

    float2 z[7][2];
    #pragma unroll
    for (int r = 0; r < 2; r++) {
        int n2 = 32 * r + s;
        float2 xin[7];
        #pragma unroll
        for (int n1 = 0; n1 < 7; n1++) xin[n1] = tile[(n1 * 64 + n2) * TSTR8 + g];
        float2 y[7];
        dft7<false>(xin, y);
        float2 wstep = sW[n2];
        float2 cur = make_float2(1.f, 0.f);
        #pragma unroll
        for (int k1 = 0; k1 < 7; k1++) {
            z[k1][r] = cmulf(y[k1], cur);
            cur = cmulf(cur, wstep);
        }
    }
    float2 ws   = sW[7   * s];
    float2 tw16 = sW[14  * (s & 15)];
    float2 tw8  = sW[28  * (s & 7)];
    float2 tw4  = sW[56  * (s & 3)];
    float2 tw2  = sW[112 * (s & 1)];
    const float* mbase = g_maskf + (size_t)(w0 + g) * 14 * 32 + s;

    #pragma unroll
    for (int k1 = 0; k1 < 7; k1++) {
        float2 e = cadd(z[k1][0], z[k1][1]);
        float2 o = cmulf(csub(z[k1][0], z[k1][1]), ws);
        float2 vv[2]; vv[0] = e; vv[1] = o;
        #pragma unroll
        for (int km = 0; km < 2; km++) {
            float2 v = vv[km];
            bfly(v, s, 16, tw16);
            bfly(v, s,  8, tw8);
            bfly(v, s,  4, tw4);
            bfly(v, s,  2, tw2);
            float2 ox;
            ox.x = __shfl_xor_sync(0xffffffffu, v.x, 1);
            ox.y = __shfl_xor_sync(0xffffffffu, v.y, 1);
            v = (s & 1) ? make_float2(ox.x - v.x, ox.y - v.y)
                        : make_float2(v.x + ox.x, v.y + ox.y);
            float mv = mbase[(km * 7 + k1) * 32];
            v.x *= mv; v.y *= mv;
            ox.x = __shfl_xor_sync(0xffffffffu, v.x, 1);
            ox.y = __shfl_xor_sync(0xffffffffu, v.y, 1);
            v = (s & 1) ? csub(ox, v) : cadd(v, ox);
            ibfly(v, s,  2, tw2);
            ibfly(v, s,  4, tw4);
            ibfly(v, s,  8, tw8);
            ibfly(v, s, 16, tw16);
            vv[km] = v;
        }
        float2 oc = cmulf(vv[1], make_float2(ws.x, -ws.y));
        z[k1][0] = cadd(vv[0], oc);
        z[k1][1] = csub(vv[0], oc);
    }

    #pragma unroll
    for (int r = 0; r < 2; r++) {
        int n2 = 32 * r + s;
        float2 wstep = sW[n2]; wstep.y = -wstep.y;
        float2 cur = make_float2(1.f, 0.f);
        float2 y[7];
        #pragma unroll
        for (int k1 = 0; k1 < 7; k1++) {
            y[k1] = cmulf(z[k1][r], cur);
            cur = cmulf(cur, wstep);
        }
        float2 xo[7];
        dft7<true>(y, xo);
        #pragma unroll
        for (int n1 = 0; n1 < 7; n1++)
            tile[(n1 * 64 + n2) * TSTR8 + g] = xo[n1];
    }
    __syncthreads();
    for (int i = 0; i < 14; i++) {
        int h = ls + 32 * i;
        gbase[h * Wd + w0 + lg] = tile[h * TSTR8 + lg];
    }
}

// -------- K3: DIT inverse row FFTs + conj-coil combine + q; partials --------
__global__ __launch_bounds__(256) void k_rowfft_inv(const float* __restrict__ cr,
                                                    const float* __restrict__ ci,
                                                    const float* __restrict__ miu,
                                                    int it) {
    int last = (it == 4);
    __shared__ float2 sW[224];
    int tid = threadIdx.x;
    for (int i = tid; i < 224; i += 256) sW[i] = g_W224[i];
    __syncthreads();
    int warp = tid >> 5, t = tid & 31;
    float2 tw16 = sW[7  * (t & 15)];
    float2 tw8  = sW[14 * (t & 7)];
    float2 tw4  = sW[28 * (t & 3)];
    float2 tw2  = sW[56 * (t & 1)];
    int rid = blockIdx.x * 8 + warp;                 // < 5376 = D*H
    int h = rid % Hd;
    float2 accq[7];
    #pragma unroll
    for (int n1 = 0; n1 < 7; n1++) accq[n1] = make_float2(0.f, 0.f);
    float2 ynext[7];
    {
        const float2* srow = g_scr + (size_t)rid * Wd;
        #pragma unroll
        for (int k1 = 0; k1 < 7; k1++) ynext[k1] = srow[k1 * 32 + t];
    }
    for (int c = 0; c < Cd; c++) {
        float2 y[7];
        #pragma unroll
        for (int k1 = 0; k1 < 7; k1++) y[k1] = ynext[k1];
        if (c + 1 < Cd) {
            const float2* srow = g_scr + ((size_t)(c + 1) * DHW + (size_t)rid * Wd);
            #pragma unroll
            for (int k1 = 0; k1 < 7; k1++) ynext[k1] = srow[k1 * 32 + t];
        }
        const float* crr = cr + (c * Hd + h) * Wd;
        const float* cii = ci + (c * Hd + h) * Wd;
        float2 co[7];
        #pragma unroll
        for (int n1 = 0; n1 < 7; n1++) {
            int x = n1 * 32 + t;
            co[n1] = make_float2(crr[x], -cii[x]);
        }
        float2 xo[7];
        fft224_inv(sW, t, tw16, tw8, tw4, tw2, y, xo);
        #pragma unroll
        for (int n1 = 0; n1 < 7; n1++) cmadd(accq[n1], xo[n1], co[n1]);
    }
    float mu = fabsf(miu[0]);
    float2 qp = make_float2(0.f, 0.f);
    float2 rq = make_float2(0.f, 0.f);
    float qq = 0.f;
    const float2* prow = g_p2[it & 1] + (size_t)rid * Wd;
    const float2* rrow = g_r2[it & 1] + (size_t)rid * Wd;
    float2* qrow = g_q + (size_t)rid * Wd;
    if (!last) {
        #pragma unroll
        for (int n1 = 0; n1 < 7; n1++) {
            int x = n1 * 32 + t;
            float2 p = prow[x];
            float2 rv = rrow[x];
            float2 q = make_float2(fmaf(mu, p.x, accq[n1].x), fmaf(mu, p.y, accq[n1].y));
            qrow[x] = q;
            qp.x += q.x * p.x + q.y * p.y;
            qp.y += q.y * p.x - q.x * p.y;
            rq.x += rv.x * q.x + rv.y * q.y;
            rq.y += rv.y * q.x - rv.x * q.y;
            qq = fmaf(q.x, q.x, fmaf(q.y, q.y, qq));
        }
    } else {
        #pragma unroll
        for (int n1 = 0; n1 < 7; n1++) {
            int x = n1 * 32 + t;
            float2 p = prow[x];
            float2 q = make_float2(fmaf(mu, p.x, accq[n1].x), fmaf(mu, p.y, accq[n1].y));
            qp.x += q.x * p.x + q.y * p.y;
            qp.y += q.y * p.x - q.x * p.y;
        }
    }
    qp = blockReduceC(qp);
    if (!last) {
        rq = blockReduceC(rq);
        qq = blockReduceF(qq);
    }
    if (tid == 0) {
        g_qp_part[blockIdx.x] = qp;
        if (!last) {
            g_rq_part[blockIdx.x] = rq;
            g_qq_part[blockIdx.x] = qq;
        }
    }
}

// -------- k_final: al4 from qp partials (redundant per block); out = checker(b + al4*p4) --------
__global__ __launch_bounds__(256) void k_final(float* __restrict__ out) {
    __shared__ float2 s_al;
    int tid = threadIdx.x;
    float2 qp = make_float2(0.f, 0.f);
    for (int i = tid; i < NB_Q; i += 256) { qp.x += g_qp_part[i].x; qp.y += g_qp_part[i].y; }
    qp = blockReduceC(qp);
    if (tid == 0) {
        float rrv = g_rr[4];
        float den = qp.x * qp.x + qp.y * qp.y;
        s_al = make_float2(rrv * qp.x / den, -rrv * qp.y / den);
    }
    __syncthreads();
    float2 al = s_al;
    const float4* p4 = (const float4*)g_p2[0];       // p for it=4 lives in buf 0
    const float4* b4 = (const float4*)g_b;
    float2* outr = (float2*)out;
    float2* outi = (float2*)(out + DHW);
    for (int n = blockIdx.x * 256 + tid; n < DHW / 2; n += NB_F * 256) {
        float4 p = p4[n], b = b4[n];
        float b0x = b.x + al.x * p.x - al.y * p.y;
        float b0y = b.y + al.x * p.y + al.y * p.x;
        float b1x = b.z + al.x * p.z - al.y * p.w;
        float b1y = b.w + al.x * p.w + al.y * p.z;
        int n2 = 2 * n;
        int w = n2 % Wd;
        int h = (n2 / Wd) % Hd;
        float s0 = ((h + w) & 1) ? -1.f : 1.f;       // w+1 flips parity
        outr[n] = make_float2(s0 * b0x, -s0 * b1x);
        outi[n] = make_float2(s0 * b0y, -s0 * b1y);
    }
}

extern "C" void kernel_launch(void* const* d_in, const int* in_sizes, int n_in,
                              void* d_out, int out_size) {
    const float* z    = (const float*)d_in[0];
    const float* zf   = (const float*)d_in[1];
    const float* cr   = (const float*)d_in[2];
    const float* ci   = (const float*)d_in[3];
    const int*   mask = (const int*)d_in[4];
    const float* miu  = (const float*)d_in[5];
    float* out = (float*)d_out;

    const int k2_shmem = 448 * TSTR8 * (int)sizeof(float2) + 448 * (int)sizeof(float2); // 35840
    cudaFuncSetAttribute(k_colfft, cudaFuncAttributeMaxDynamicSharedMemorySize, k2_shmem);

    k_setup<<<(HW + 255) / 256, 256>>>(mask);
    k_init<<<NB_EW, 256>>>(z, zf, miu);
    for (int it = 0; it < 5; ++it) {
        k_rowfft_fwd<<<6720, 256>>>(cr, ci, it);       // C*D*H/8 (+fused CG update for it>0)
        k_colfft<<<3360, 256, k2_shmem>>>();           // C*D*(W/8)
        k_rowfft_inv<<<NB_Q, 256>>>(cr, ci, miu, it);  // D*H/8
        if (it < 4) k_scalar<<<1, 256>>>(it);          // al/be/rr for the fused update
    }
    k_final<<<NB_F, 256>>>(out);
}

// round 15
// speedup vs baseline: 1.0734x; 1.0734x over previous
#include <cuda_runtime.h>
#include <math.h>

// Problem dims
#define Hd   448
#define Wd   224
#define Dd   12
#define Cd   10
#define HW   100352          // 448*224
#define DHW  1204224         // 12*HW
#define CDHW 12042240        // 10*DHW
#define INV_HW (1.0f/100352.0f)
#define NB_EW 1024           // blocks for elementwise+reduce kernels
#define NB_Q  672            // blocks for K3 (D*H/8)
#define PI_D 3.14159265358979323846
#define TSTR8 9              // padded tile stride (float2) for K2 (8-col tiles)

// -------- device scratch (static __device__ arrays: allocation-free) --------
__device__ float2 g_scr[CDHW];     // coil-expanded k-rows, w PERMUTED: j=32*k1+t <-> w=7*bitrev5(t)+k1
__device__ float2 g_p[DHW];
__device__ float2 g_r[DHW];
__device__ float2 g_b[DHW];
__device__ float2 g_q[DHW];
__device__ float2 g_W224[224];
__device__ float2 g_W448[448];
__device__ float  g_maskf[HW];     // permuted mask * INV_HW, layout [w][km][k1][s]
__device__ float2 g_qp_part[NB_Q];
__device__ float2 g_rq_part[NB_Q];
__device__ float  g_qq_part[NB_Q];
__device__ float  g_rrp[NB_EW];    // ||r0||^2 partials (from k_init)
__device__ float  g_rr[8];         // rr chain: g_rr[it]

// -------- complex helpers (scalar — keeps register allocation lean) --------
__device__ __forceinline__ float2 cmulf(float2 a, float2 b) {
    return make_float2(a.x*b.x - a.y*b.y, a.x*b.y + a.y*b.x);
}
__device__ __forceinline__ void cmadd(float2& acc, float2 a, float2 b) {
    acc.x = fmaf(a.x, b.x, fmaf(-a.y, b.y, acc.x));
    acc.y = fmaf(a.x, b.y, fmaf( a.y, b.x, acc.y));
}
__device__ __forceinline__ float2 cadd(float2 a, float2 b){ return make_float2(a.x+b.x, a.y+b.y); }
__device__ __forceinline__ float2 csub(float2 a, float2 b){ return make_float2(a.x-b.x, a.y-b.y); }

__device__ __forceinline__ int bitrev5(int t) {
    return ((t & 1) << 4) | ((t & 2) << 2) | (t & 4) | ((t & 8) >> 2) | ((t & 16) >> 4);
}

// -------- symmetric DFT-7 (real-immediate coefficients) --------
template<bool INV>
__device__ __forceinline__ void dft7(const float2 x[7], float2 X[7]) {
    const float C1f =  0.62348980185873359f;
    const float C2f = -0.22252093395631440f;
    const float C3f = -0.90096886790241915f;
    const float S1f =  0.78183148246802981f;
    const float S2f =  0.97492791218182360f;
    const float S3f =  0.43388373911755812f;
    float2 a1 = cadd(x[1], x[6]), b1 = csub(x[1], x[6]);
    float2 a2 = cadd(x[2], x[5]), b2 = csub(x[2], x[5]);
    float2 a3 = cadd(x[3], x[4]), b3 = csub(x[3], x[4]);
    X[0] = make_float2(x[0].x + a1.x + a2.x + a3.x,
                       x[0].y + a1.y + a2.y + a3.y);
    float2 u1, u2, u3, v1, v2, v3;
    u1.x = fmaf(C1f,a1.x, fmaf(C2f,a2.x, fmaf(C3f,a3.x, x[0].x)));
    u1.y = fmaf(C1f,a1.y, fmaf(C2f,a2.y, fmaf(C3f,a3.y, x[0].y)));
    u2.x = fmaf(C2f,a1.x, fmaf(C3f,a2.x, fmaf(C1f,a3.x, x[0].x)));
    u2.y = fmaf(C2f,a1.y, fmaf(C3f,a2.y, fmaf(C1f,a3.y, x[0].y)));
    u3.x = fmaf(C3f,a1.x, fmaf(C1f,a2.x, fmaf(C2f,a3.x, x[0].x)));
    u3.y = fmaf(C3f,a1.y, fmaf(C1f,a2.y, fmaf(C2f,a3.y, x[0].y)));
    v1.x = fmaf(S1f,b1.x, fmaf( S2f,b2.x,  S3f*b3.x));
    v1.y = fmaf(S1f,b1.y, fmaf( S2f,b2.y,  S3f*b3.y));
    v2.x = fmaf(S2f,b1.x, fmaf(-S3f,b2.x, -S1f*b3.x));
    v2.y = fmaf(S2f,b1.y, fmaf(-S3f,b2.y, -S1f*b3.y));
    v3.x = fmaf(S3f,b1.x, fmaf(-S1f,b2.x,  S2f*b3.x));
    v3.y = fmaf(S3f,b1.y, fmaf(-S1f,b2.y,  S2f*b3.y));
    if (!INV) {
        X[1] = make_float2(u1.x + v1.y, u1.y - v1.x);
        X[6] = make_float2(u1.x - v1.y, u1.y + v1.x);
        X[2] = make_float2(u2.x + v2.y, u2.y - v2.x);
        X[5] = make_float2(u2.x - v2.y, u2.y + v2.x);
        X[3] = make_float2(u3.x + v3.y, u3.y - v3.x);
        X[4] = make_float2(u3.x - v3.y, u3.y + v3.x);
    } else {
        X[1] = make_float2(u1.x - v1.y, u1.y + v1.x);
        X[6] = make_float2(u1.x + v1.y, u1.y - v1.x);
        X[2] = make_float2(u2.x - v2.y, u2.y + v2.x);
        X[5] = make_float2(u2.x + v2.y, u2.y - v2.x);
        X[3] = make_float2(u3.x - v3.y, u3.y + v3.x);
        X[4] = make_float2(u3.x + v3.y, u3.y - v3.x);
    }
}

// forward radix-2 DIF butterfly across lanes
__device__ __forceinline__ void bfly(float2& v, int t, int m, float2 tw) {
    float2 o;
    o.x = __shfl_xor_sync(0xffffffffu, v.x, m);
    o.y = __shfl_xor_sync(0xffffffffu, v.y, m);
    float2 sum = make_float2(v.x + o.x, v.y + o.y);
    float2 dif = make_float2(o.x - v.x, o.y - v.y);
    float2 dm  = cmulf(dif, tw);
    v = (t & m) ? dm : sum;
}

// inverse radix-2 DIT butterfly (tw = FORWARD stage twiddle; conj applied inline)
__device__ __forceinline__ void ibfly(float2& v, int t, int m, float2 tw) {
    float2 twc = make_float2(tw.x, -tw.y);
    float2 vv = v;
    if (t & m) vv = cmulf(v, twc);
    float2 o;
    o.x = __shfl_xor_sync(0xffffffffu, vv.x, m);
    o.y = __shfl_xor_sync(0xffffffffu, vv.y, m);
    v = (t & m) ? csub(o, vv) : cadd(vv, o);
}

// -------- deterministic block reductions (trailing sync: safe to call repeatedly) --------
__device__ __forceinline__ float blockReduceF(float v) {
    __shared__ float red[8];
    int lane = threadIdx.x & 31, wp = threadIdx.x >> 5;
    #pragma unroll
    for (int o = 16; o > 0; o >>= 1) v += __shfl_down_sync(0xffffffffu, v, o);
    if (lane == 0) red[wp] = v;
    __syncthreads();
    if (wp == 0) {
        v = (lane < 8) ? red[lane] : 0.f;
        #pragma unroll
        for (int o = 4; o > 0; o >>= 1) v += __shfl_down_sync(0xffffffffu, v, o);
    }
    __syncthreads();
    return v;   // valid on thread 0
}
__device__ __forceinline__ float2 blockReduceC(float2 v) {
    __shared__ float2 redc[8];
    int lane = threadIdx.x & 31, wp = threadIdx.x >> 5;
    #pragma unroll
    for (int o = 16; o > 0; o >>= 1) {
        v.x += __shfl_down_sync(0xffffffffu, v.x, o);
        v.y += __shfl_down_sync(0xffffffffu, v.y, o);
    }
    if (lane == 0) redc[wp] = v;
    __syncthreads();
    if (wp == 0) {
        v = (lane < 8) ? redc[lane] : make_float2(0.f, 0.f);
        #pragma unroll
        for (int o = 4; o > 0; o >>= 1) {
            v.x += __shfl_down_sync(0xffffffffu, v.x, o);
            v.y += __shfl_down_sync(0xffffffffu, v.y, o);
        }
    }
    __syncthreads();
    return v;
}

// -------- fused setup: twiddles + permuted mask table, layout [w][km][k1][s] --------
__global__ void k_setup(const int* __restrict__ mask) {
    int idx = blockIdx.x * 256 + threadIdx.x;
    if (idx < 224) {
        double a = -2.0 * PI_D * (double)idx / 224.0;
        g_W224[idx] = make_float2((float)cos(a), (float)sin(a));
    }
    if (idx < 448) {
        double a = -2.0 * PI_D * (double)idx / 448.0;
        g_W448[idx] = make_float2((float)cos(a), (float)sin(a));
    }
    if (idx < HW) {
        int s = idx & 31;
        int rest = idx >> 5;          // (j*2+km)*7 + k1
        int k1 = rest % 7;
        int q = rest / 7;             // j*2 + km
        int km = q & 1;
        int j = q >> 1;
        int t = j & 31, k1w = j >> 5;
        int wt = 7 * bitrev5(t) + k1w;
        int ktrue = 7 * (2 * bitrev5(s) + km) + k1;
        g_maskf[idx] = mask[ktrue * Wd + wt] ? INV_HW : 0.f;
    }
}

// -------- forward 224-pt FFT per warp: symmetric radix-7 + shuffle DIF FFT-32.
__device__ __forceinline__ void fft224_fwd(const float2* sW, int t,
        float2 tw16, float2 tw8, float2 tw4, float2 tw2,
        const float2 a[7], float2 out[7]) {
    float2 y[7];
    dft7<false>(a, y);
    float2 wstep = sW[t];
    float2 cur = make_float2(1.f, 0.f);
    #pragma unroll
    for (int k1 = 0; k1 < 7; k1++) {
        float2 v = cmulf(y[k1], cur);
        cur = cmulf(cur, wstep);
        bfly(v, t, 16, tw16);
        bfly(v, t,  8, tw8);
        bfly(v, t,  4, tw4);
        bfly(v, t,  2, tw2);
        float2 o;
        o.x = __shfl_xor_sync(0xffffffffu, v.x, 1);
        o.y = __shfl_xor_sync(0xffffffffu, v.y, 1);
        v = (t & 1) ? make_float2(o.x - v.x, o.y - v.y)
                    : make_float2(v.x + o.x, v.y + o.y);
        out[k1] = v;
    }
}

// -------- inverse 224-pt FFT per warp, consuming permuted (DIF) order natively.
__device__ __forceinline__ void fft224_inv(const float2* sW, int t,
        float2 tw16, float2 tw8, float2 tw4, float2 tw2,
        float2 y[7], float2 xo[7]) {
    float2 wstep = sW[t]; wstep.y = -wstep.y;          // conj(W224^t)
    float2 cur = make_float2(1.f, 0.f);
    #pragma unroll
    for (int k1 = 0; k1 < 7; k1++) {
        float2 v = y[k1];
        float2 o;                                      // stage m=1: plain
        o.x = __shfl_xor_sync(0xffffffffu, v.x, 1);
        o.y = __shfl_xor_sync(0xffffffffu, v.y, 1);
        v = (t & 1) ? csub(o, v) : cadd(v, o);
        ibfly(v, t,  2, tw2);
        ibfly(v, t,  4, tw4);
        ibfly(v, t,  8, tw8);
        ibfly(v, t, 16, tw16);
        y[k1] = cmulf(v, cur);
        cur = cmulf(cur, wstep);
    }
    dft7<true>(y, xo);
}

// -------- K0: p = s*(zf + mu*z); partial ||p||^2.  (r0 ≡ p0, b0 ≡ 0 analytically) --------
__global__ __launch_bounds__(256) void k_init(const float* __restrict__ z,
                                              const float* __restrict__ zf,
                                              const float* __restrict__ miu) {
    float mu = fabsf(miu[0]);
    float rr = 0.f;
    for (int n = blockIdx.x * 256 + threadIdx.x; n < DHW; n += NB_EW * 256) {
        int w = n % Wd;
        int h = (n / Wd) % Hd;
        float s = ((h + w) & 1) ? -1.f : 1.f;
        float pr = s * (zf[n] + mu * z[n]);
        float pi = s * (zf[DHW + n] + mu * z[DHW + n]);
        g_p[n] = make_float2(pr, pi);
        rr = fmaf(pr, pr, fmaf(pi, pi, rr));
    }
    rr = blockReduceF(rr);
    if (threadIdx.x == 0) g_rrp[blockIdx.x] = rr;
}

// -------- K1: forward row FFTs with coil expand (pure; p is pre-updated) --------
__global__ __launch_bounds__(256) void k_rowfft_fwd(const float* __restrict__ cr,
                                                    const float* __restrict__ ci) {
    __shared__ float2 sW[224];
    int tid = threadIdx.x;
    for (int i = tid; i < 224; i += 256) sW[i] = g_W224[i];
    __syncthreads();
    int warp = tid >> 5, t = tid & 31;
    float2 tw16 = sW[7  * (t & 15)];
    float2 tw8  = sW[14 * (t & 7)];
    float2 tw4  = sW[28 * (t & 3)];
    float2 tw2  = sW[56 * (t & 1)];
    int rid = blockIdx.x * 8 + warp;                 // < 53760
    int c = rid / (Dd * Hd);
    int r2 = rid - c * (Dd * Hd);
    int h = r2 % Hd;
    const float2* prow = g_p + r2 * Wd;
    const float* crr = cr + (c * Hd + h) * Wd;
    const float* cii = ci + (c * Hd + h) * Wd;
    float2 a[7];
    #pragma unroll
    for (int n1 = 0; n1 < 7; n1++) {
        int idx = n1 * 32 + t;
        float2 p = prow[idx];
        float2 co = make_float2(crr[idx], cii[idx]);
        a[n1] = cmulf(p, co);
    }
    float2 out[7];
    fft224_fwd(sW, t, tw16, tw8, tw4, tw2, a, out);
    float2* orow = g_scr + (size_t)rid * Wd;
    #pragma unroll
    for (int k1 = 0; k1 < 7; k1++) orow[k1 * 32 + t] = out[k1];   // permuted, coalesced
}

// -------- K2: warp-per-column 448-pt FFT + mask + IFFT, 8-column tiles --------
__global__ void __launch_bounds__(256, 3) k_colfft() {
    extern __shared__ float2 sh[];                   // tile[448*TSTR8] ++ W448[448]
    float2* tile = sh;
    float2* sW = sh + 448 * TSTR8;
    int tid = threadIdx.x;
    for (int i = tid; i < 448; i += 256) sW[i] = g_W448[i];
    int wt = blockIdx.x % 28;                        // 28 tiles of 8 columns
    int cd = blockIdx.x / 28;                        // c*D + d
    int w0 = wt * 8;
    float2* gbase = g_scr + (size_t)cd * HW;
    int lg = tid & 7, ls = tid >> 3;                 // I/O roles
    int g = tid >> 5, s = tid & 31;                  // compute roles: warp g owns column w0+g
    for (int i = 0; i < 14; i++) {
        int h = ls + 32 * i;
        tile[h * TSTR8 + lg] = gbase[h * Wd + w0 + lg];
    }
    __syncthreads();

    // ---- stage 1 (forward): radix-7 over n1 + chained twiddle W448^{n2*k1} ----
    float2 z[7][2];
    #pragma unroll
    for (int r = 0; r < 2; r++) {
        int n2 = 32 * r + s;
        float2 xin[7];
        #pragma unroll
        for (int n1 = 0; n1 < 7; n1++) xin[n1] = tile[(n1 * 64 + n2) * TSTR8 + g];
        float2 y[7];
        dft7<false>(xin, y);
        float2 wstep = sW[n2];
        float2 cur = make_float2(1.f, 0.f);
        #pragma unroll
        for (int k1 = 0; k1 < 7; k1++) {
            z[k1][r] = cmulf(y[k1], cur);
            cur = cmulf(cur, wstep);
        }
    }
    float2 ws   = sW[7   * s];           // W64^s
    float2 tw16 = sW[14  * (s & 15)];    // W32^{s&15}
    float2 tw8  = sW[28  * (s & 7)];     // W16^{s&7}
    float2 tw4  = sW[56  * (s & 3)];     // W8^{s&3}
    float2 tw2  = sW[112 * (s & 1)];     // W4^{s&1}
    const float* mbase = g_maskf + (size_t)(w0 + g) * 14 * 32 + s;  // [w][km][k1][s]

    // ---- per-k1: radix-2 local + lane FFT-32 + mask + lane IFFT-32 + local inverse ----
    #pragma unroll
    for (int k1 = 0; k1 < 7; k1++) {
        float2 e = cadd(z[k1][0], z[k1][1]);
        float2 o = cmulf(csub(z[k1][0], z[k1][1]), ws);
        float2 vv[2]; vv[0] = e; vv[1] = o;
        #pragma unroll
        for (int km = 0; km < 2; km++) {
            float2 v = vv[km];
            bfly(v, s, 16, tw16);
            bfly(v, s,  8, tw8);
            bfly(v, s,  4, tw4);
            bfly(v, s,  2, tw2);
            float2 ox;
            ox.x = __shfl_xor_sync(0xffffffffu, v.x, 1);
            ox.y = __shfl_xor_sync(0xffffffffu, v.y, 1);
            v = (s & 1) ? make_float2(ox.x - v.x, ox.y - v.y)
                        : make_float2(v.x + ox.x, v.y + ox.y);
            float mv = mbase[(km * 7 + k1) * 32];
            v.x *= mv; v.y *= mv;
            ox.x = __shfl_xor_sync(0xffffffffu, v.x, 1);
            ox.y = __shfl_xor_sync(0xffffffffu, v.y, 1);
            v = (s & 1) ? csub(ox, v) : cadd(v, ox);
            ibfly(v, s,  2, tw2);
            ibfly(v, s,  4, tw4);
            ibfly(v, s,  8, tw8);
            ibfly(v, s, 16, tw16);
            vv[km] = v;                              // natural n index = s
        }
        float2 oc = cmulf(vv[1], make_float2(ws.x, -ws.y));
        z[k1][0] = cadd(vv[0], oc);
        z[k1][1] = csub(vv[0], oc);
    }

    // ---- final stage (inverse): chained conj twiddle + inverse radix-7 -> tile ----
    #pragma unroll
    for (int r = 0; r < 2; r++) {
        int n2 = 32 * r + s;
        float2 wstep = sW[n2]; wstep.y = -wstep.y;
        float2 cur = make_float2(1.f, 0.f);
        float2 y[7];
        #pragma unroll
        for (int k1 = 0; k1 < 7; k1++) {
            y[k1] = cmulf(z[k1][r], cur);
            cur = cmulf(cur, wstep);
        }
        float2 xo[7];
        dft7<true>(y, xo);
        #pragma unroll
        for (int n1 = 0; n1 < 7; n1++)
            tile[(n1 * 64 + n2) * TSTR8 + g] = xo[n1];   // this thread's own slots
    }
    __syncthreads();
    for (int i = 0; i < 14; i++) {
        int h = ls + 32 * i;
        gbase[h * Wd + w0 + lg] = tile[h * TSTR8 + lg];
    }
}

// -------- K3: DIT inverse row FFTs + conj-coil combine + q; partials qp (,rq, qq) --------
// Software-pipelined over coils. it==0: r ≡ p (skip r load). it==4: only qp needed.
__global__ __launch_bounds__(256) void k_rowfft_inv(const float* __restrict__ cr,
                                                    const float* __restrict__ ci,
                                                    const float* __restrict__ miu,
                                                    int it) {
    int last = (it == 4);
    __shared__ float2 sW[224];
    int tid = threadIdx.x;
    for (int i = tid; i < 224; i += 256) sW[i] = g_W224[i];
    __syncthreads();
    int warp = tid >> 5, t = tid & 31;
    float2 tw16 = sW[7  * (t & 15)];
    float2 tw8  = sW[14 * (t & 7)];
    float2 tw4  = sW[28 * (t & 3)];
    float2 tw2  = sW[56 * (t & 1)];
    int rid = blockIdx.x * 8 + warp;                 // < 5376 = D*H
    int h = rid % Hd;
    float2 accq[7];
    #pragma unroll
    for (int n1 = 0; n1 < 7; n1++) accq[n1] = make_float2(0.f, 0.f);
    float2 ynext[7];
    {
        const float2* srow = g_scr + (size_t)rid * Wd;
        #pragma unroll
        for (int k1 = 0; k1 < 7; k1++) ynext[k1] = srow[k1 * 32 + t];
    }
    for (int c = 0; c < Cd; c++) {
        float2 y[7];
        #pragma unroll
        for (int k1 = 0; k1 < 7; k1++) y[k1] = ynext[k1];
        if (c + 1 < Cd) {
            const float2* srow = g_scr + ((size_t)(c + 1) * DHW + (size_t)rid * Wd);
            #pragma unroll
            for (int k1 = 0; k1 < 7; k1++) ynext[k1] = srow[k1 * 32 + t];
        }
        const float* crr = cr + (c * Hd + h) * Wd;
        const float* cii = ci + (c * Hd + h) * Wd;
        float2 co[7];
        #pragma unroll
        for (int n1 = 0; n1 < 7; n1++) {
            int x = n1 * 32 + t;
            co[n1] = make_float2(crr[x], -cii[x]);
        }
        float2 xo[7];
        fft224_inv(sW, t, tw16, tw8, tw4, tw2, y, xo);
        #pragma unroll
        for (int n1 = 0; n1 < 7; n1++) cmadd(accq[n1], xo[n1], co[n1]);
    }
    float mu = fabsf(miu[0]);
    float2 qp = make_float2(0.f, 0.f);
    float2 rq = make_float2(0.f, 0.f);
    float qq = 0.f;
    const float2* prow = g_p + (size_t)rid * Wd;
    const float2* rrow = g_r + (size_t)rid * Wd;
    float2* qrow = g_q + (size_t)rid * Wd;
    if (!last) {
        #pragma unroll
        for (int n1 = 0; n1 < 7; n1++) {
            int x = n1 * 32 + t;
            float2 p = prow[x];
            float2 rv = (it == 0) ? p : rrow[x];     // r0 ≡ p0
            float2 q = make_float2(fmaf(mu, p.x, accq[n1].x), fmaf(mu, p.y, accq[n1].y));
            qrow[x] = q;
            qp.x += q.x * p.x + q.y * p.y;
            qp.y += q.y * p.x - q.x * p.y;
            rq.x += rv.x * q.x + rv.y * q.y;
            rq.y += rv.y * q.x - rv.x * q.y;
            qq = fmaf(q.x, q.x, fmaf(q.y, q.y, qq));
        }
    } else {
        #pragma unroll
        for (int n1 = 0; n1 < 7; n1++) {
            int x = n1 * 32 + t;
            float2 p = prow[x];
            float2 q = make_float2(fmaf(mu, p.x, accq[n1].x), fmaf(mu, p.y, accq[n1].y));
            qp.x += q.x * p.x + q.y * p.y;
            qp.y += q.y * p.x - q.x * p.y;
        }
    }
    qp = blockReduceC(qp);
    if (!last) {
        rq = blockReduceC(rq);
        qq = blockReduceF(qq);
    }
    if (tid == 0) {
        g_qp_part[blockIdx.x] = qp;
        if (!last) {
            g_rq_part[blockIdx.x] = rq;
            g_qq_part[blockIdx.x] = qq;
        }
    }
}

// -------- fused: alpha + analytic rr_new + beta; b += al p; r -= al q; p = r + be p --------
// float4-vectorized. it==0 uses r ≡ p, b ≡ 0 (no r/b loads). Last iteration writes output.
__global__ __launch_bounds__(256) void k_update_br(int it, float* __restrict__ out) {
    __shared__ float2 s_al;
    __shared__ float s_be;
    int tid = threadIdx.x;
    float2 qp = make_float2(0.f, 0.f), rq = make_float2(0.f, 0.f);
    float qq = 0.f;
    if (it < 4) {
        for (int i = tid; i < NB_Q; i += 256) {
            qp.x += g_qp_part[i].x; qp.y += g_qp_part[i].y;
            rq.x += g_rq_part[i].x; rq.y += g_rq_part[i].y;
            qq += g_qq_part[i];
        }
        qp = blockReduceC(qp);
        rq = blockReduceC(rq);
        qq = blockReduceF(qq);
    } else {
        for (int i = tid; i < NB_Q; i += 256) {
            qp.x += g_qp_part[i].x; qp.y += g_qp_part[i].y;
        }
        qp = blockReduceC(qp);
    }
    float rr0 = 0.f;
    if (it == 0) {
        float v = 0.f;
        for (int i = tid; i < NB_EW; i += 256) v += g_rrp[i];
        rr0 = blockReduceF(v);
    }
    if (tid == 0) {
        float rrv = (it == 0) ? rr0 : g_rr[it];
        float den = qp.x * qp.x + qp.y * qp.y;
        float2 al = make_float2(rrv * qp.x / den, -rrv * qp.y / den);
        s_al = al;
        if (it < 4) {
            float rr_new = rrv - 2.f * (al.x * rq.x + al.y * rq.y)
                         + (al.x * al.x + al.y * al.y) * qq;
            s_be = rr_new / rrv;
            if (blockIdx.x == 0) g_rr[it + 1] = rr_new;
        }
    }
    __syncthreads();
    float2 al = s_al;
    const float4* p4 = (const float4*)g_p;
    float4* b4 = (float4*)g_b;
    if (it < 4) {
        float be = s_be;
        const float4* q4 = (const float4*)g_q;
        float4* r4 = (float4*)g_r;
        float4* p4w = (float4*)g_p;
        for (int n = blockIdx.x * 256 + tid; n < DHW / 2; n += NB_EW * 256) {
            float4 p = p4[n], q = q4[n];
            float4 b, r;
            if (it == 0) {
                r = p;
                b = make_float4(0.f, 0.f, 0.f, 0.f);
            } else {
                r = r4[n];
                b = b4[n];
            }
            b.x += al.x * p.x - al.y * p.y;
            b.y += al.x * p.y + al.y * p.x;
            b.z += al.x * p.z - al.y * p.w;
            b.w += al.x * p.w + al.y * p.z;
            float r0x = r.x - (al.x * q.x - al.y * q.y);
            float r0y = r.y - (al.x * q.y + al.y * q.x);
            float r1x = r.z - (al.x * q.z - al.y * q.w);
            float r1y = r.w - (al.x * q.w + al.y * q.z);
            b4[n] = b;
            r4[n] = make_float4(r0x, r0y, r1x, r1y);
            p4w[n] = make_float4(fmaf(be, p.x, r0x), fmaf(be, p.y, r0y),
                                 fmaf(be, p.z, r1x), fmaf(be, p.w, r1y));
        }
    } else {
        float2* outr = (float2*)out;
        float2* outi = (float2*)(out + DHW);
        for (int n = blockIdx.x * 256 + tid; n < DHW / 2; n += NB_EW * 256) {
            float4 p = p4[n], b = b4[n];
            float b0x = b.x + al.x * p.x - al.y * p.y;
            float b0y = b.y + al.x * p.y + al.y * p.x;
            float b1x = b.z + al.x * p.z - al.y * p.w;
            float b1y = b.w + al.x * p.w + al.y * p.z;
            int n2 = 2 * n;
            int w = n2 % Wd;
            int h = (n2 / Wd) % Hd;
            float s0 = ((h + w) & 1) ? -1.f : 1.f;   // w+1 flips parity
            outr[n] = make_float2(s0 * b0x, -s0 * b1x);
            outi[n] = make_float2(s0 * b0y, -s0 * b1y);
        }
    }
}

extern "C" void kernel_launch(void* const* d_in, const int* in_sizes, int n_in,
                              void* d_out, int out_size) {
    const float* z    = (const float*)d_in[0];
    const float* zf   = (const float*)d_in[1];
    const float* cr   = (const float*)d_in[2];
    const float* ci   = (const float*)d_in[3];
    const int*   mask = (const int*)d_in[4];
    const float* miu  = (const float*)d_in[5];
    float* out = (float*)d_out;

    const int k2_shmem = 448 * TSTR8 * (int)sizeof(float2) + 448 * (int)sizeof(float2); // 35840
    cudaFuncSetAttribute(k_colfft, cudaFuncAttributeMaxDynamicSharedMemorySize, k2_shmem);

    k_setup<<<(HW + 255) / 256, 256>>>(mask);
    k_init<<<NB_EW, 256>>>(z, zf, miu);
    for (int it = 0; it < 5; ++it) {
        k_rowfft_fwd<<<6720, 256>>>(cr, ci);           // C*D*H/8
        k_colfft<<<3360, 256, k2_shmem>>>();           // C*D*(W/8)
        k_rowfft_inv<<<NB_Q, 256>>>(cr, ci, miu, it);  // D*H/8
        k_update_br<<<NB_EW, 256>>>(it, out);          // al (+rr_new, be); updates b,r,p / writes out
    }
}

// round 16
// speedup vs baseline: 1.1855x; 1.1044x over previous
#include <cuda_runtime.h>
#include <math.h>

// Problem dims
#define Hd   448
#define Wd   224
#define Dd   12
#define Cd   10
#define HW   100352          // 448*224
#define DHW  1204224         // 12*HW
#define CDHW 12042240        // 10*DHW
#define INV_HW (1.0f/100352.0f)
#define NB_EW 1024           // blocks for elementwise+reduce kernels
#define NB_Q  1344           // blocks for K3 (D*H/4, 4 warps per CTA)
#define PI_D 3.14159265358979323846
#define TSTR8 9              // padded tile stride (float2) for K2 (8-col tiles)

// -------- device scratch (static __device__ arrays: allocation-free) --------
__device__ float2 g_scr[CDHW];     // coil-expanded k-rows, w PERMUTED: j=32*k1+t <-> w=7*bitrev5(t)+k1
__device__ float2 g_p[DHW];
__device__ float2 g_r[DHW];
__device__ float2 g_b[DHW];
__device__ float2 g_q[DHW];
__device__ float2 g_W224[224];
__device__ float2 g_W448[448];
__device__ float  g_maskf[HW];     // permuted mask * INV_HW, layout [w][km][k1][s]
__device__ float2 g_qp_part[NB_Q];
__device__ float2 g_rq_part[NB_Q];
__device__ float  g_qq_part[NB_Q];
__device__ float  g_rrp[NB_EW];    // ||r0||^2 partials (from k_init)
__device__ float  g_rr[8];         // rr chain: g_rr[it]

// -------- complex helpers (scalar — keeps register allocation lean) --------
__device__ __forceinline__ float2 cmulf(float2 a, float2 b) {
    return make_float2(a.x*b.x - a.y*b.y, a.x*b.y + a.y*b.x);
}
__device__ __forceinline__ void cmadd(float2& acc, float2 a, float2 b) {
    acc.x = fmaf(a.x, b.x, fmaf(-a.y, b.y, acc.x));
    acc.y = fmaf(a.x, b.y, fmaf( a.y, b.x, acc.y));
}
__device__ __forceinline__ float2 cadd(float2 a, float2 b){ return make_float2(a.x+b.x, a.y+b.y); }
__device__ __forceinline__ float2 csub(float2 a, float2 b){ return make_float2(a.x-b.x, a.y-b.y); }

__device__ __forceinline__ int bitrev5(int t) {
    return ((t & 1) << 4) | ((t & 2) << 2) | (t & 4) | ((t & 8) >> 2) | ((t & 16) >> 4);
}

// -------- symmetric DFT-7 (real-immediate coefficients) --------
template<bool INV>
__device__ __forceinline__ void dft7(const float2 x[7], float2 X[7]) {
    const float C1f =  0.62348980185873359f;
    const float C2f = -0.22252093395631440f;
    const float C3f = -0.90096886790241915f;
    const float S1f =  0.78183148246802981f;
    const float S2f =  0.97492791218182360f;
    const float S3f =  0.43388373911755812f;
    float2 a1 = cadd(x[1], x[6]), b1 = csub(x[1], x[6]);
    float2 a2 = cadd(x[2], x[5]), b2 = csub(x[2], x[5]);
    float2 a3 = cadd(x[3], x[4]), b3 = csub(x[3], x[4]);
    X[0] = make_float2(x[0].x + a1.x + a2.x + a3.x,
                       x[0].y + a1.y + a2.y + a3.y);
    float2 u1, u2, u3, v1, v2, v3;
    u1.x = fmaf(C1f,a1.x, fmaf(C2f,a2.x, fmaf(C3f,a3.x, x[0].x)));
    u1.y = fmaf(C1f,a1.y, fmaf(C2f,a2.y, fmaf(C3f,a3.y, x[0].y)));
    u2.x = fmaf(C2f,a1.x, fmaf(C3f,a2.x, fmaf(C1f,a3.x, x[0].x)));
    u2.y = fmaf(C2f,a1.y, fmaf(C3f,a2.y, fmaf(C1f,a3.y, x[0].y)));
    u3.x = fmaf(C3f,a1.x, fmaf(C1f,a2.x, fmaf(C2f,a3.x, x[0].x)));
    u3.y = fmaf(C3f,a1.y, fmaf(C1f,a2.y, fmaf(C2f,a3.y, x[0].y)));
    v1.x = fmaf(S1f,b1.x, fmaf( S2f,b2.x,  S3f*b3.x));
    v1.y = fmaf(S1f,b1.y, fmaf( S2f,b2.y,  S3f*b3.y));
    v2.x = fmaf(S2f,b1.x, fmaf(-S3f,b2.x, -S1f*b3.x));
    v2.y = fmaf(S2f,b1.y, fmaf(-S3f,b2.y, -S1f*b3.y));
    v3.x = fmaf(S3f,b1.x, fmaf(-S1f,b2.x,  S2f*b3.x));
    v3.y = fmaf(S3f,b1.y, fmaf(-S1f,b2.y,  S2f*b3.y));
    if (!INV) {
        X[1] = make_float2(u1.x + v1.y, u1.y - v1.x);
        X[6] = make_float2(u1.x - v1.y, u1.y + v1.x);
        X[2] = make_float2(u2.x + v2.y, u2.y - v2.x);
        X[5] = make_float2(u2.x - v2.y, u2.y + v2.x);
        X[3] = make_float2(u3.x + v3.y, u3.y - v3.x);
        X[4] = make_float2(u3.x - v3.y, u3.y + v3.x);
    } else {
        X[1] = make_float2(u1.x - v1.y, u1.y + v1.x);
        X[6] = make_float2(u1.x + v1.y, u1.y - v1.x);
        X[2] = make_float2(u2.x - v2.y, u2.y + v2.x);
        X[5] = make_float2(u2.x + v2.y, u2.y - v2.x);
        X[3] = make_float2(u3.x - v3.y, u3.y + v3.x);
        X[4] = make_float2(u3.x + v3.y, u3.y - v3.x);
    }
}

// forward radix-2 DIF butterfly across lanes
__device__ __forceinline__ void bfly(float2& v, int t, int m, float2 tw) {
    float2 o;
    o.x = __shfl_xor_sync(0xffffffffu, v.x, m);
    o.y = __shfl_xor_sync(0xffffffffu, v.y, m);
    float2 sum = make_float2(v.x + o.x, v.y + o.y);
    float2 dif = make_float2(o.x - v.x, o.y - v.y);
    float2 dm  = cmulf(dif, tw);
    v = (t & m) ? dm : sum;
}

// inverse radix-2 DIT butterfly (tw = FORWARD stage twiddle; conj applied inline)
__device__ __forceinline__ void ibfly(float2& v, int t, int m, float2 tw) {
    float2 twc = make_float2(tw.x, -tw.y);
    float2 vv = v;
    if (t & m) vv = cmulf(v, twc);
    float2 o;
    o.x = __shfl_xor_sync(0xffffffffu, vv.x, m);
    o.y = __shfl_xor_sync(0xffffffffu, vv.y, m);
    v = (t & m) ? csub(o, vv) : cadd(vv, o);
}

// -------- deterministic block reductions (NW = warps per block; trailing sync) --------
template<int NW>
__device__ __forceinline__ float blockReduceF(float v) {
    __shared__ float red[8];
    int lane = threadIdx.x & 31, wp = threadIdx.x >> 5;
    #pragma unroll
    for (int o = 16; o > 0; o >>= 1) v += __shfl_down_sync(0xffffffffu, v, o);
    if (lane == 0) red[wp] = v;
    __syncthreads();
    if (wp == 0) {
        v = (lane < NW) ? red[lane] : 0.f;
        #pragma unroll
        for (int o = 4; o > 0; o >>= 1) v += __shfl_down_sync(0xffffffffu, v, o);
    }
    __syncthreads();
    return v;   // valid on thread 0
}
template<int NW>
__device__ __forceinline__ float2 blockReduceC(float2 v) {
    __shared__ float2 redc[8];
    int lane = threadIdx.x & 31, wp = threadIdx.x >> 5;
    #pragma unroll
    for (int o = 16; o > 0; o >>= 1) {
        v.x += __shfl_down_sync(0xffffffffu, v.x, o);
        v.y += __shfl_down_sync(0xffffffffu, v.y, o);
    }
    if (lane == 0) redc[wp] = v;
    __syncthreads();
    if (wp == 0) {
        v = (lane < NW) ? redc[lane] : make_float2(0.f, 0.f);
        #pragma unroll
        for (int o = 4; o > 0; o >>= 1) {
            v.x += __shfl_down_sync(0xffffffffu, v.x, o);
            v.y += __shfl_down_sync(0xffffffffu, v.y, o);
        }
    }
    __syncthreads();
    return v;
}

// -------- fused setup: twiddles + permuted mask table, layout [w][km][k1][s] --------
__global__ void k_setup(const int* __restrict__ mask) {
    int idx = blockIdx.x * 256 + threadIdx.x;
    if (idx < 224) {
        double a = -2.0 * PI_D * (double)idx / 224.0;
        g_W224[idx] = make_float2((float)cos(a), (float)sin(a));
    }
    if (idx < 448) {
        double a = -2.0 * PI_D * (double)idx / 448.0;
        g_W448[idx] = make_float2((float)cos(a), (float)sin(a));
    }
    if (idx < HW) {
        int s = idx & 31;
        int rest = idx >> 5;          // (j*2+km)*7 + k1
        int k1 = rest % 7;
        int q = rest / 7;             // j*2 + km
        int km = q & 1;
        int j = q >> 1;
        int t = j & 31, k1w = j >> 5;
        int wt = 7 * bitrev5(t) + k1w;
        int ktrue = 7 * (2 * bitrev5(s) + km) + k1;
        g_maskf[idx] = mask[ktrue * Wd + wt] ? INV_HW : 0.f;
    }
}

// -------- forward 224-pt FFT per warp: symmetric radix-7 + shuffle DIF FFT-32.
__device__ __forceinline__ void fft224_fwd(const float2* sW, int t,
        float2 tw16, float2 tw8, float2 tw4, float2 tw2,
        const float2 a[7], float2 out[7]) {
    float2 y[7];
    dft7<false>(a, y);
    float2 wstep = sW[t];
    float2 cur = make_float2(1.f, 0.f);
    #pragma unroll
    for (int k1 = 0; k1 < 7; k1++) {
        float2 v = cmulf(y[k1], cur);
        cur = cmulf(cur, wstep);
        bfly(v, t, 16, tw16);
        bfly(v, t,  8, tw8);
        bfly(v, t,  4, tw4);
        bfly(v, t,  2, tw2);
        float2 o;
        o.x = __shfl_xor_sync(0xffffffffu, v.x, 1);
        o.y = __shfl_xor_sync(0xffffffffu, v.y, 1);
        v = (t & 1) ? make_float2(o.x - v.x, o.y - v.y)
                    : make_float2(v.x + o.x, v.y + o.y);
        out[k1] = v;
    }
}

// -------- inverse 224-pt FFT per warp, consuming permuted (DIF) order natively.
__device__ __forceinline__ void fft224_inv(const float2* sW, int t,
        float2 tw16, float2 tw8, float2 tw4, float2 tw2,
        float2 y[7], float2 xo[7]) {
    float2 wstep = sW[t]; wstep.y = -wstep.y;          // conj(W224^t)
    float2 cur = make_float2(1.f, 0.f);
    #pragma unroll
    for (int k1 = 0; k1 < 7; k1++) {
        float2 v = y[k1];
        float2 o;                                      // stage m=1: plain
        o.x = __shfl_xor_sync(0xffffffffu, v.x, 1);
        o.y = __shfl_xor_sync(0xffffffffu, v.y, 1);
        v = (t & 1) ? csub(o, v) : cadd(v, o);
        ibfly(v, t,  2, tw2);
        ibfly(v, t,  4, tw4);
        ibfly(v, t,  8, tw8);
        ibfly(v, t, 16, tw16);
        y[k1] = cmulf(v, cur);
        cur = cmulf(cur, wstep);
    }
    dft7<true>(y, xo);
}

// -------- K0: p = s*(zf + mu*z); partial ||p||^2.  (r0 ≡ p0, b0 ≡ 0 analytically) --------
__global__ __launch_bounds__(256) void k_init(const float* __restrict__ z,
                                              const float* __restrict__ zf,
                                              const float* __restrict__ miu) {
    float mu = fabsf(miu[0]);
    float rr = 0.f;
    for (int n = blockIdx.x * 256 + threadIdx.x; n < DHW; n += NB_EW * 256) {
        int w = n % Wd;
        int h = (n / Wd) % Hd;
        float s = ((h + w) & 1) ? -1.f : 1.f;
        float pr = s * (zf[n] + mu * z[n]);
        float pi = s * (zf[DHW + n] + mu * z[DHW + n]);
        g_p[n] = make_float2(pr, pi);
        rr = fmaf(pr, pr, fmaf(pi, pi, rr));
    }
    rr = blockReduceF<8>(rr);
    if (threadIdx.x == 0) g_rrp[blockIdx.x] = rr;
}

// -------- K1: forward row FFTs with coil expand (pure; p is pre-updated) --------
__global__ __launch_bounds__(256) void k_rowfft_fwd(const float* __restrict__ cr,
                                                    const float* __restrict__ ci) {
    __shared__ float2 sW[224];
    int tid = threadIdx.x;
    for (int i = tid; i < 224; i += 256) sW[i] = g_W224[i];
    __syncthreads();
    int warp = tid >> 5, t = tid & 31;
    float2 tw16 = sW[7  * (t & 15)];
    float2 tw8  = sW[14 * (t & 7)];
    float2 tw4  = sW[28 * (t & 3)];
    float2 tw2  = sW[56 * (t & 1)];
    int rid = blockIdx.x * 8 + warp;                 // < 53760
    int c = rid / (Dd * Hd);
    int r2 = rid - c * (Dd * Hd);
    int h = r2 % Hd;
    const float2* prow = g_p + r2 * Wd;
    const float* crr = cr + (c * Hd + h) * Wd;
    const float* cii = ci + (c * Hd + h) * Wd;
    float2 a[7];
    #pragma unroll
    for (int n1 = 0; n1 < 7; n1++) {
        int idx = n1 * 32 + t;
        float2 p = prow[idx];
        float2 co = make_float2(crr[idx], cii[idx]);
        a[n1] = cmulf(p, co);
    }
    float2 out[7];
    fft224_fwd(sW, t, tw16, tw8, tw4, tw2, a, out);
    float2* orow = g_scr + (size_t)rid * Wd;
    #pragma unroll
    for (int k1 = 0; k1 < 7; k1++) orow[k1 * 32 + t] = out[k1];   // permuted, coalesced
}

// -------- K2: warp-per-column 448-pt FFT + mask + IFFT, 8-column tiles --------
__global__ void __launch_bounds__(256, 3) k_colfft() {
    extern __shared__ float2 sh[];                   // tile[448*TSTR8] ++ W448[448]
    float2* tile = sh;
    float2* sW = sh + 448 * TSTR8;
    int tid = threadIdx.x;
    for (int i = tid; i < 448; i += 256) sW[i] = g_W448[i];
    int wt = blockIdx.x % 28;                        // 28 tiles of 8 columns
    int cd = blockIdx.x / 28;                        // c*D + d
    int w0 = wt * 8;
    float2* gbase = g_scr + (size_t)cd * HW;
    int lg = tid & 7, ls = tid >> 3;                 // I/O roles
    int g = tid >> 5, s = tid & 31;                  // compute roles: warp g owns column w0+g
    for (int i = 0; i < 14; i++) {
        int h = ls + 32 * i;
        tile[h * TSTR8 + lg] = gbase[h * Wd + w0 + lg];
    }
    __syncthreads();

    // ---- stage 1 (forward): radix-7 over n1 + chained twiddle W448^{n2*k1} ----
    float2 z[7][2];
    #pragma unroll
    for (int r = 0; r < 2; r++) {
        int n2 = 32 * r + s;
        float2 xin[7];
        #pragma unroll
        for (int n1 = 0; n1 < 7; n1++) xin[n1] = tile[(n1 * 64 + n2) * TSTR8 + g];
        float2 y[7];
        dft7<false>(xin, y);
        float2 wstep = sW[n2];
        float2 cur = make_float2(1.f, 0.f);
        #pragma unroll
        for (int k1 = 0; k1 < 7; k1++) {
            z[k1][r] = cmulf(y[k1], cur);
            cur = cmulf(cur, wstep);
        }
    }
    float2 ws   = sW[7   * s];           // W64^s
    float2 tw16 = sW[14  * (s & 15)];    // W32^{s&15}
    float2 tw8  = sW[28  * (s & 7)];     // W16^{s&7}
    float2 tw4  = sW[56  * (s & 3)];     // W8^{s&3}
    float2 tw2  = sW[112 * (s & 1)];     // W4^{s&1}
    const float* mbase = g_maskf + (size_t)(w0 + g) * 14 * 32 + s;  // [w][km][k1][s]

    // ---- per-k1: radix-2 local + lane FFT-32 + mask + lane IFFT-32 + local inverse ----
    #pragma unroll
    for (int k1 = 0; k1 < 7; k1++) {
        float2 e = cadd(z[k1][0], z[k1][1]);
        float2 o = cmulf(csub(z[k1][0], z[k1][1]), ws);
        float2 vv[2]; vv[0] = e; vv[1] = o;
        #pragma unroll
        for (int km = 0; km < 2; km++) {
            float2 v = vv[km];
            bfly(v, s, 16, tw16);
            bfly(v, s,  8, tw8);
            bfly(v, s,  4, tw4);
            bfly(v, s,  2, tw2);
            float2 ox;
            ox.x = __shfl_xor_sync(0xffffffffu, v.x, 1);
            ox.y = __shfl_xor_sync(0xffffffffu, v.y, 1);
            v = (s & 1) ? make_float2(ox.x - v.x, ox.y - v.y)
                        : make_float2(v.x + ox.x, v.y + ox.y);
            float mv = mbase[(km * 7 + k1) * 32];
            v.x *= mv; v.y *= mv;
            ox.x = __shfl_xor_sync(0xffffffffu, v.x, 1);
            ox.y = __shfl_xor_sync(0xffffffffu, v.y, 1);
            v = (s & 1) ? csub(ox, v) : cadd(v, ox);
            ibfly(v, s,  2, tw2);
            ibfly(v, s,  4, tw4);
            ibfly(v, s,  8, tw8);
            ibfly(v, s, 16, tw16);
            vv[km] = v;                              // natural n index = s
        }
        float2 oc = cmulf(vv[1], make_float2(ws.x, -ws.y));
        z[k1][0] = cadd(vv[0], oc);
        z[k1][1] = csub(vv[0], oc);
    }

    // ---- final stage (inverse): chained conj twiddle + inverse radix-7 -> tile ----
    #pragma unroll
    for (int r = 0; r < 2; r++) {
        int n2 = 32 * r + s;
        float2 wstep = sW[n2]; wstep.y = -wstep.y;
        float2 cur = make_float2(1.f, 0.f);
        float2 y[7];
        #pragma unroll
        for (int k1 = 0; k1 < 7; k1++) {
            y[k1] = cmulf(z[k1][r], cur);
            cur = cmulf(cur, wstep);
        }
        float2 xo[7];
        dft7<true>(y, xo);
        #pragma unroll
        for (int n1 = 0; n1 < 7; n1++)
            tile[(n1 * 64 + n2) * TSTR8 + g] = xo[n1];   // this thread's own slots
    }
    __syncthreads();
    for (int i = 0; i < 14; i++) {
        int h = ls + 32 * i;
        gbase[h * Wd + w0 + lg] = tile[h * TSTR8 + lg];
    }
}

// -------- K3: DIT inverse row FFTs + conj-coil combine + q; partials qp (,rq, qq) --------
// 128-thread CTAs (4 warps, 1 row/warp) for finer wave granularity + higher residency.
__global__ __launch_bounds__(128) void k_rowfft_inv(const float* __restrict__ cr,
                                                    const float* __restrict__ ci,
                                                    const float* __restrict__ miu,
                                                    int it) {
    int last = (it == 4);
    __shared__ float2 sW[224];
    int tid = threadIdx.x;
    for (int i = tid; i < 224; i += 128) sW[i] = g_W224[i];
    __syncthreads();
    int warp = tid >> 5, t = tid & 31;
    float2 tw16 = sW[7  * (t & 15)];
    float2 tw8  = sW[14 * (t & 7)];
    float2 tw4  = sW[28 * (t & 3)];
    float2 tw2  = sW[56 * (t & 1)];
    int rid = blockIdx.x * 4 + warp;                 // < 5376 = D*H
    int h = rid % Hd;
    float2 accq[7];
    #pragma unroll
    for (int n1 = 0; n1 < 7; n1++) accq[n1] = make_float2(0.f, 0.f);
    float2 ynext[7];
    {
        const float2* srow = g_scr + (size_t)rid * Wd;
        #pragma unroll
        for (int k1 = 0; k1 < 7; k1++) ynext[k1] = srow[k1 * 32 + t];
    }
    for (int c = 0; c < Cd; c++) {
        float2 y[7];
        #pragma unroll
        for (int k1 = 0; k1 < 7; k1++) y[k1] = ynext[k1];
        if (c + 1 < Cd) {
            const float2* srow = g_scr + ((size_t)(c + 1) * DHW + (size_t)rid * Wd);
            #pragma unroll
            for (int k1 = 0; k1 < 7; k1++) ynext[k1] = srow[k1 * 32 + t];
        }
        const float* crr = cr + (c * Hd + h) * Wd;
        const float* cii = ci + (c * Hd + h) * Wd;
        float2 co[7];
        #pragma unroll
        for (int n1 = 0; n1 < 7; n1++) {
            int x = n1 * 32 + t;
            co[n1] = make_float2(crr[x], -cii[x]);
        }
        float2 xo[7];
        fft224_inv(sW, t, tw16, tw8, tw4, tw2, y, xo);
        #pragma unroll
        for (int n1 = 0; n1 < 7; n1++) cmadd(accq[n1], xo[n1], co[n1]);
    }
    float mu = fabsf(miu[0]);
    float2 qp = make_float2(0.f, 0.f);
    float2 rq = make_float2(0.f, 0.f);
    float qq = 0.f;
    const float2* prow = g_p + (size_t)rid * Wd;
    const float2* rrow = g_r + (size_t)rid * Wd;
    float2* qrow = g_q + (size_t)rid * Wd;
    if (!last) {
        #pragma unroll
        for (int n1 = 0; n1 < 7; n1++) {
            int x = n1 * 32 + t;
            float2 p = prow[x];
            float2 rv = (it == 0) ? p : rrow[x];     // r0 ≡ p0
            float2 q = make_float2(fmaf(mu, p.x, accq[n1].x), fmaf(mu, p.y, accq[n1].y));
            qrow[x] = q;
            qp.x += q.x * p.x + q.y * p.y;
            qp.y += q.y * p.x - q.x * p.y;
            rq.x += rv.x * q.x + rv.y * q.y;
            rq.y += rv.y * q.x - rv.x * q.y;
            qq = fmaf(q.x, q.x, fmaf(q.y, q.y, qq));
        }
    } else {
        #pragma unroll
        for (int n1 = 0; n1 < 7; n1++) {
            int x = n1 * 32 + t;
            float2 p = prow[x];
            float2 q = make_float2(fmaf(mu, p.x, accq[n1].x), fmaf(mu, p.y, accq[n1].y));
            qp.x += q.x * p.x + q.y * p.y;
            qp.y += q.y * p.x - q.x * p.y;
        }
    }
    qp = blockReduceC<4>(qp);
    if (!last) {
        rq = blockReduceC<4>(rq);
        qq = blockReduceF<4>(qq);
    }
    if (tid == 0) {
        g_qp_part[blockIdx.x] = qp;
        if (!last) {
            g_rq_part[blockIdx.x] = rq;
            g_qq_part[blockIdx.x] = qq;
        }
    }
}

// -------- fused: alpha + analytic rr_new + beta; b += al p; r -= al q; p = r + be p --------
// float4-vectorized. it==0 uses r ≡ p, b ≡ 0 (no r/b loads). Last iteration writes output.
__global__ __launch_bounds__(256) void k_update_br(int it, float* __restrict__ out) {
    __shared__ float2 s_al;
    __shared__ float s_be;
    int tid = threadIdx.x;
    float2 qp = make_float2(0.f, 0.f), rq = make_float2(0.f, 0.f);
    float qq = 0.f;
    if (it < 4) {
        for (int i = tid; i < NB_Q; i += 256) {
            qp.x += g_qp_part[i].x; qp.y += g_qp_part[i].y;
            rq.x += g_rq_part[i].x; rq.y += g_rq_part[i].y;
            qq += g_qq_part[i];
        }
        qp = blockReduceC<8>(qp);
        rq = blockReduceC<8>(rq);
        qq = blockReduceF<8>(qq);
    } else {
        for (int i = tid; i < NB_Q; i += 256) {
            qp.x += g_qp_part[i].x; qp.y += g_qp_part[i].y;
        }
        qp = blockReduceC<8>(qp);
    }
    float rr0 = 0.f;
    if (it == 0) {
        float v = 0.f;
        for (int i = tid; i < NB_EW; i += 256) v += g_rrp[i];
        rr0 = blockReduceF<8>(v);
    }
    if (tid == 0) {
        float rrv = (it == 0) ? rr0 : g_rr[it];
        float den = qp.x * qp.x + qp.y * qp.y;
        float2 al = make_float2(rrv * qp.x / den, -rrv * qp.y / den);
        s_al = al;
        if (it < 4) {
            float rr_new = rrv - 2.f * (al.x * rq.x + al.y * rq.y)
                         + (al.x * al.x + al.y * al.y) * qq;
            s_be = rr_new / rrv;
            if (blockIdx.x == 0) g_rr[it + 1] = rr_new;
        }
    }
    __syncthreads();
    float2 al = s_al;
    const float4* p4 = (const float4*)g_p;
    float4* b4 = (float4*)g_b;
    if (it < 4) {
        float be = s_be;
        const float4* q4 = (const float4*)g_q;
        float4* r4 = (float4*)g_r;
        float4* p4w = (float4*)g_p;
        for (int n = blockIdx.x * 256 + tid; n < DHW / 2; n += NB_EW * 256) {
            float4 p = p4[n], q = q4[n];
            float4 b, r;
            if (it == 0) {
                r = p;
                b = make_float4(0.f, 0.f, 0.f, 0.f);
            } else {
                r = r4[n];
                b = b4[n];
            }
            b.x += al.x * p.x - al.y * p.y;
            b.y += al.x * p.y + al.y * p.x;
            b.z += al.x * p.z - al.y * p.w;
            b.w += al.x * p.w + al.y * p.z;
            float r0x = r.x - (al.x * q.x - al.y * q.y);
            float r0y = r.y - (al.x * q.y + al.y * q.x);
            float r1x = r.z - (al.x * q.z - al.y * q.w);
            float r1y = r.w - (al.x * q.w + al.y * q.z);
            b4[n] = b;
            r4[n] = make_float4(r0x, r0y, r1x, r1y);
            p4w[n] = make_float4(fmaf(be, p.x, r0x), fmaf(be, p.y, r0y),
                                 fmaf(be, p.z, r1x), fmaf(be, p.w, r1y));
        }
    } else {
        float2* outr = (float2*)out;
        float2* outi = (float2*)(out + DHW);
        for (int n = blockIdx.x * 256 + tid; n < DHW / 2; n += NB_EW * 256) {
            float4 p = p4[n], b = b4[n];
            float b0x = b.x + al.x * p.x - al.y * p.y;
            float b0y = b.y + al.x * p.y + al.y * p.x;
            float b1x = b.z + al.x * p.z - al.y * p.w;
            float b1y = b.w + al.x * p.w + al.y * p.z;
            int n2 = 2 * n;
            int w = n2 % Wd;
            int h = (n2 / Wd) % Hd;
            float s0 = ((h + w) & 1) ? -1.f : 1.f;   // w+1 flips parity
            outr[n] = make_float2(s0 * b0x, -s0 * b1x);
            outi[n] = make_float2(s0 * b0y, -s0 * b1y);
        }
    }
}

extern "C" void kernel_launch(void* const* d_in, const int* in_sizes, int n_in,
                              void* d_out, int out_size) {
    const float* z    = (const float*)d_in[0];
    const float* zf   = (const float*)d_in[1];
    const float* cr   = (const float*)d_in[2];
    const float* ci   = (const float*)d_in[3];
    const int*   mask = (const int*)d_in[4];
    const float* miu  = (const float*)d_in[5];
    float* out = (float*)d_out;

    const int k2_shmem = 448 * TSTR8 * (int)sizeof(float2) + 448 * (int)sizeof(float2); // 35840
    cudaFuncSetAttribute(k_colfft, cudaFuncAttributeMaxDynamicSharedMemorySize, k2_shmem);

    k_setup<<<(HW + 255) / 256, 256>>>(mask);
    k_init<<<NB_EW, 256>>>(z, zf, miu);
    for (int it = 0; it < 5; ++it) {
        k_rowfft_fwd<<<6720, 256>>>(cr, ci);           // C*D*H/8
        k_colfft<<<3360, 256, k2_shmem>>>();           // C*D*(W/8)
        k_rowfft_inv<<<NB_Q, 128>>>(cr, ci, miu, it);  // D*H/4, 4 warps/CTA
        k_update_br<<<NB_EW, 256>>>(it, out);          // al (+rr_new, be); updates b,r,p / writes out
    }
}

// round 17
// speedup vs baseline: 1.1955x; 1.0084x over previous
#include <cuda_runtime.h>
#include <math.h>

// Problem dims
#define Hd   448
#define Wd   224
#define Dd   12
#define Cd   10
#define HW   100352          // 448*224
#define DHW  1204224         // 12*HW
#define CDHW 12042240        // 10*DHW
#define INV_HW (1.0f/100352.0f)
#define NB_EW 1024           // blocks for elementwise+reduce kernels
#define NB_Q  1344           // blocks for K3 (D*H/4, 4 warps per CTA)
#define PI_D 3.14159265358979323846
#define TSTR8 9              // padded tile stride (float2) for K2 (8-col tiles)

// -------- device scratch (static __device__ arrays: allocation-free) --------
__device__ float2 g_scr[CDHW];     // coil-expanded k-rows, w PERMUTED: j=32*k1+t <-> w=7*bitrev5(t)+k1
__device__ float2 g_p[DHW];
__device__ float2 g_r[DHW];
__device__ float2 g_b[DHW];
__device__ float2 g_q[DHW];
__device__ float2 g_W224[224];
__device__ float2 g_W448[448];
__device__ float  g_maskf[HW];     // permuted mask * INV_HW, layout [w][km][k1][s]
__device__ float2 g_qp_part[NB_Q];
__device__ float2 g_rq_part[NB_Q];
__device__ float  g_qq_part[NB_Q];
__device__ float  g_rrp[NB_EW];    // ||r0||^2 partials (from k_init)
__device__ float  g_rr[8];         // rr chain: g_rr[it]

// -------- complex helpers (scalar — keeps register allocation lean) --------
__device__ __forceinline__ float2 cmulf(float2 a, float2 b) {
    return make_float2(a.x*b.x - a.y*b.y, a.x*b.y + a.y*b.x);
}
__device__ __forceinline__ void cmadd(float2& acc, float2 a, float2 b) {
    acc.x = fmaf(a.x, b.x, fmaf(-a.y, b.y, acc.x));
    acc.y = fmaf(a.x, b.y, fmaf( a.y, b.x, acc.y));
}
__device__ __forceinline__ float2 cadd(float2 a, float2 b){ return make_float2(a.x+b.x, a.y+b.y); }
__device__ __forceinline__ float2 csub(float2 a, float2 b){ return make_float2(a.x-b.x, a.y-b.y); }

__device__ __forceinline__ int bitrev5(int t) {
    return ((t & 1) << 4) | ((t & 2) << 2) | (t & 4) | ((t & 8) >> 2) | ((t & 16) >> 4);
}

// -------- symmetric DFT-7 (real-immediate coefficients) --------
template<bool INV>
__device__ __forceinline__ void dft7(const float2 x[7], float2 X[7]) {
    const float C1f =  0.62348980185873359f;
    const float C2f = -0.22252093395631440f;
    const float C3f = -0.90096886790241915f;
    const float S1f =  0.78183148246802981f;
    const float S2f =  0.97492791218182360f;
    const float S3f =  0.43388373911755812f;
    float2 a1 = cadd(x[1], x[6]), b1 = csub(x[1], x[6]);
    float2 a2 = cadd(x[2], x[5]), b2 = csub(x[2], x[5]);
    float2 a3 = cadd(x[3], x[4]), b3 = csub(x[3], x[4]);
    X[0] = make_float2(x[0].x + a1.x + a2.x + a3.x,
                       x[0].y + a1.y + a2.y + a3.y);
    float2 u1, u2, u3, v1, v2, v3;
    u1.x = fmaf(C1f,a1.x, fmaf(C2f,a2.x, fmaf(C3f,a3.x, x[0].x)));
    u1.y = fmaf(C1f,a1.y, fmaf(C2f,a2.y, fmaf(C3f,a3.y, x[0].y)));
    u2.x = fmaf(C2f,a1.x, fmaf(C3f,a2.x, fmaf(C1f,a3.x, x[0].x)));
    u2.y = fmaf(C2f,a1.y, fmaf(C3f,a2.y, fmaf(C1f,a3.y, x[0].y)));
    u3.x = fmaf(C3f,a1.x, fmaf(C1f,a2.x, fmaf(C2f,a3.x, x[0].x)));
    u3.y = fmaf(C3f,a1.y, fmaf(C1f,a2.y, fmaf(C2f,a3.y, x[0].y)));
    v1.x = fmaf(S1f,b1.x, fmaf( S2f,b2.x,  S3f*b3.x));
    v1.y = fmaf(S1f,b1.y, fmaf( S2f,b2.y,  S3f*b3.y));
    v2.x = fmaf(S2f,b1.x, fmaf(-S3f,b2.x, -S1f*b3.x));
    v2.y = fmaf(S2f,b1.y, fmaf(-S3f,b2.y, -S1f*b3.y));
    v3.x = fmaf(S3f,b1.x, fmaf(-S1f,b2.x,  S2f*b3.x));
    v3.y = fmaf(S3f,b1.y, fmaf(-S1f,b2.y,  S2f*b3.y));
    if (!INV) {
        X[1] = make_float2(u1.x + v1.y, u1.y - v1.x);
        X[6] = make_float2(u1.x - v1.y, u1.y + v1.x);
        X[2] = make_float2(u2.x + v2.y, u2.y - v2.x);
        X[5] = make_float2(u2.x - v2.y, u2.y + v2.x);
        X[3] = make_float2(u3.x + v3.y, u3.y - v3.x);
        X[4] = make_float2(u3.x - v3.y, u3.y + v3.x);
    } else {
        X[1] = make_float2(u1.x - v1.y, u1.y + v1.x);
        X[6] = make_float2(u1.x + v1.y, u1.y - v1.x);
        X[2] = make_float2(u2.x - v2.y, u2.y + v2.x);
        X[5] = make_float2(u2.x + v2.y, u2.y - v2.x);
        X[3] = make_float2(u3.x - v3.y, u3.y + v3.x);
        X[4] = make_float2(u3.x + v3.y, u3.y - v3.x);
    }
}

// forward radix-2 DIF butterfly across lanes
__device__ __forceinline__ void bfly(float2& v, int t, int m, float2 tw) {
    float2 o;
    o.x = __shfl_xor_sync(0xffffffffu, v.x, m);
    o.y = __shfl_xor_sync(0xffffffffu, v.y, m);
    float2 sum = make_float2(v.x + o.x, v.y + o.y);
    float2 dif = make_float2(o.x - v.x, o.y - v.y);
    float2 dm  = cmulf(dif, tw);
    v = (t & m) ? dm : sum;
}

// inverse radix-2 DIT butterfly (tw = FORWARD stage twiddle; conj applied inline)
__device__ __forceinline__ void ibfly(float2& v, int t, int m, float2 tw) {
    float2 twc = make_float2(tw.x, -tw.y);
    float2 vv = v;
    if (t & m) vv = cmulf(v, twc);
    float2 o;
    o.x = __shfl_xor_sync(0xffffffffu, vv.x, m);
    o.y = __shfl_xor_sync(0xffffffffu, vv.y, m);
    v = (t & m) ? csub(o, vv) : cadd(vv, o);
}

// -------- deterministic block reductions (NW = warps per block; trailing sync) --------
template<int NW>
__device__ __forceinline__ float blockReduceF(float v) {
    __shared__ float red[8];
    int lane = threadIdx.x & 31, wp = threadIdx.x >> 5;
    #pragma unroll
    for (int o = 16; o > 0; o >>= 1) v += __shfl_down_sync(0xffffffffu, v, o);
    if (lane == 0) red[wp] = v;
    __syncthreads();
    if (wp == 0) {
        v = (lane < NW) ? red[lane] : 0.f;
        #pragma unroll
        for (int o = 4; o > 0; o >>= 1) v += __shfl_down_sync(0xffffffffu, v, o);
    }
    __syncthreads();
    return v;   // valid on thread 0
}
template<int NW>
__device__ __forceinline__ float2 blockReduceC(float2 v) {
    __shared__ float2 redc[8];
    int lane = threadIdx.x & 31, wp = threadIdx.x >> 5;
    #pragma unroll
    for (int o = 16; o > 0; o >>= 1) {
        v.x += __shfl_down_sync(0xffffffffu, v.x, o);
        v.y += __shfl_down_sync(0xffffffffu, v.y, o);
    }
    if (lane == 0) redc[wp] = v;
    __syncthreads();
    if (wp == 0) {
        v = (lane < NW) ? redc[lane] : make_float2(0.f, 0.f);
        #pragma unroll
        for (int o = 4; o > 0; o >>= 1) {
            v.x += __shfl_down_sync(0xffffffffu, v.x, o);
            v.y += __shfl_down_sync(0xffffffffu, v.y, o);
        }
    }
    __syncthreads();
    return v;
}

// -------- fused setup: twiddles + permuted mask table, layout [w][km][k1][s] --------
__global__ void k_setup(const int* __restrict__ mask) {
    int idx = blockIdx.x * 256 + threadIdx.x;
    if (idx < 224) {
        double a = -2.0 * PI_D * (double)idx / 224.0;
        g_W224[idx] = make_float2((float)cos(a), (float)sin(a));
    }
    if (idx < 448) {
        double a = -2.0 * PI_D * (double)idx / 448.0;
        g_W448[idx] = make_float2((float)cos(a), (float)sin(a));
    }
    if (idx < HW) {
        int s = idx & 31;
        int rest = idx >> 5;          // (j*2+km)*7 + k1
        int k1 = rest % 7;
        int q = rest / 7;             // j*2 + km
        int km = q & 1;
        int j = q >> 1;
        int t = j & 31, k1w = j >> 5;
        int wt = 7 * bitrev5(t) + k1w;
        int ktrue = 7 * (2 * bitrev5(s) + km) + k1;
        g_maskf[idx] = mask[ktrue * Wd + wt] ? INV_HW : 0.f;
    }
}

// -------- forward 224-pt FFT per warp: symmetric radix-7 + shuffle DIF FFT-32.
__device__ __forceinline__ void fft224_fwd(const float2* sW, int t,
        float2 tw16, float2 tw8, float2 tw4, float2 tw2,
        const float2 a[7], float2 out[7]) {
    float2 y[7];
    dft7<false>(a, y);
    float2 wstep = sW[t];
    float2 cur = make_float2(1.f, 0.f);
    #pragma unroll
    for (int k1 = 0; k1 < 7; k1++) {
        float2 v = cmulf(y[k1], cur);
        cur = cmulf(cur, wstep);
        bfly(v, t, 16, tw16);
        bfly(v, t,  8, tw8);
        bfly(v, t,  4, tw4);
        bfly(v, t,  2, tw2);
        float2 o;
        o.x = __shfl_xor_sync(0xffffffffu, v.x, 1);
        o.y = __shfl_xor_sync(0xffffffffu, v.y, 1);
        v = (t & 1) ? make_float2(o.x - v.x, o.y - v.y)
                    : make_float2(v.x + o.x, v.y + o.y);
        out[k1] = v;
    }
}

// -------- inverse 224-pt FFT per warp, consuming permuted (DIF) order natively.
__device__ __forceinline__ void fft224_inv(const float2* sW, int t,
        float2 tw16, float2 tw8, float2 tw4, float2 tw2,
        float2 y[7], float2 xo[7]) {
    float2 wstep = sW[t]; wstep.y = -wstep.y;          // conj(W224^t)
    float2 cur = make_float2(1.f, 0.f);
    #pragma unroll
    for (int k1 = 0; k1 < 7; k1++) {
        float2 v = y[k1];
        float2 o;                                      // stage m=1: plain
        o.x = __shfl_xor_sync(0xffffffffu, v.x, 1);
        o.y = __shfl_xor_sync(0xffffffffu, v.y, 1);
        v = (t & 1) ? csub(o, v) : cadd(v, o);
        ibfly(v, t,  2, tw2);
        ibfly(v, t,  4, tw4);
        ibfly(v, t,  8, tw8);
        ibfly(v, t, 16, tw16);
        y[k1] = cmulf(v, cur);
        cur = cmulf(cur, wstep);
    }
    dft7<true>(y, xo);
}

// -------- K0: p = s*(zf + mu*z); partial ||p||^2.  (r0 ≡ p0, b0 ≡ 0 analytically) --------
__global__ __launch_bounds__(256) void k_init(const float* __restrict__ z,
                                              const float* __restrict__ zf,
                                              const float* __restrict__ miu) {
    float mu = fabsf(miu[0]);
    float rr = 0.f;
    for (int n = blockIdx.x * 256 + threadIdx.x; n < DHW; n += NB_EW * 256) {
        int w = n % Wd;
        int h = (n / Wd) % Hd;
        float s = ((h + w) & 1) ? -1.f : 1.f;
        float pr = s * (zf[n] + mu * z[n]);
        float pi = s * (zf[DHW + n] + mu * z[DHW + n]);
        g_p[n] = make_float2(pr, pi);
        rr = fmaf(pr, pr, fmaf(pi, pi, rr));
    }
    rr = blockReduceF<8>(rr);
    if (threadIdx.x == 0) g_rrp[blockIdx.x] = rr;
}

// -------- K1: forward row FFTs with coil expand (pure; p is pre-updated) --------
__global__ __launch_bounds__(256) void k_rowfft_fwd(const float* __restrict__ cr,
                                                    const float* __restrict__ ci) {
    __shared__ float2 sW[224];
    int tid = threadIdx.x;
    for (int i = tid; i < 224; i += 256) sW[i] = g_W224[i];
    __syncthreads();
    int warp = tid >> 5, t = tid & 31;
    float2 tw16 = sW[7  * (t & 15)];
    float2 tw8  = sW[14 * (t & 7)];
    float2 tw4  = sW[28 * (t & 3)];
    float2 tw2  = sW[56 * (t & 1)];
    int rid = blockIdx.x * 8 + warp;                 // < 53760
    int c = rid / (Dd * Hd);
    int r2 = rid - c * (Dd * Hd);
    int h = r2 % Hd;
    const float2* prow = g_p + r2 * Wd;
    const float* crr = cr + (c * Hd + h) * Wd;
    const float* cii = ci + (c * Hd + h) * Wd;
    float2 a[7];
    #pragma unroll
    for (int n1 = 0; n1 < 7; n1++) {
        int idx = n1 * 32 + t;
        float2 p = prow[idx];
        float2 co = make_float2(crr[idx], cii[idx]);
        a[n1] = cmulf(p, co);
    }
    float2 out[7];
    fft224_fwd(sW, t, tw16, tw8, tw4, tw2, a, out);
    float2* orow = g_scr + (size_t)rid * Wd;
    #pragma unroll
    for (int k1 = 0; k1 < 7; k1++) orow[k1 * 32 + t] = out[k1];   // permuted, coalesced
}

// -------- K2: warp-per-column 448-pt FFT + mask + IFFT, 8-column tiles --------
// __launch_bounds__(256, 4): target 64 regs -> 4 CTAs/SM (32 warps), up from 3.
__global__ void __launch_bounds__(256, 4) k_colfft() {
    extern __shared__ float2 sh[];                   // tile[448*TSTR8] ++ W448[448]
    float2* tile = sh;
    float2* sW = sh + 448 * TSTR8;
    int tid = threadIdx.x;
    for (int i = tid; i < 448; i += 256) sW[i] = g_W448[i];
    int wt = blockIdx.x % 28;                        // 28 tiles of 8 columns
    int cd = blockIdx.x / 28;                        // c*D + d
    int w0 = wt * 8;
    float2* gbase = g_scr + (size_t)cd * HW;
    int lg = tid & 7, ls = tid >> 3;                 // I/O roles
    int g = tid >> 5, s = tid & 31;                  // compute roles: warp g owns column w0+g
    for (int i = 0; i < 14; i++) {
        int h = ls + 32 * i;
        tile[h * TSTR8 + lg] = gbase[h * Wd + w0 + lg];
    }
    __syncthreads();

    // ---- stage 1 (forward): radix-7 over n1 + chained twiddle W448^{n2*k1} ----
    float2 z[7][2];
    #pragma unroll
    for (int r = 0; r < 2; r++) {
        int n2 = 32 * r + s;
        float2 xin[7];
        #pragma unroll
        for (int n1 = 0; n1 < 7; n1++) xin[n1] = tile[(n1 * 64 + n2) * TSTR8 + g];
        float2 y[7];
        dft7<false>(xin, y);
        float2 wstep = sW[n2];
        float2 cur = make_float2(1.f, 0.f);
        #pragma unroll
        for (int k1 = 0; k1 < 7; k1++) {
            z[k1][r] = cmulf(y[k1], cur);
            cur = cmulf(cur, wstep);
        }
    }
    float2 ws   = sW[7   * s];           // W64^s
    float2 tw16 = sW[14  * (s & 15)];    // W32^{s&15}
    float2 tw8  = sW[28  * (s & 7)];     // W16^{s&7}
    float2 tw4  = sW[56  * (s & 3)];     // W8^{s&3}
    float2 tw2  = sW[112 * (s & 1)];     // W4^{s&1}
    const float* mbase = g_maskf + (size_t)(w0 + g) * 14 * 32 + s;  // [w][km][k1][s]

    // ---- per-k1: radix-2 local + lane FFT-32 + mask + lane IFFT-32 + local inverse ----
    #pragma unroll
    for (int k1 = 0; k1 < 7; k1++) {
        float2 e = cadd(z[k1][0], z[k1][1]);
        float2 o = cmulf(csub(z[k1][0], z[k1][1]), ws);
        float2 vv[2]; vv[0] = e; vv[1] = o;
        #pragma unroll
        for (int km = 0; km < 2; km++) {
            float2 v = vv[km];
            bfly(v, s, 16, tw16);
            bfly(v, s,  8, tw8);
            bfly(v, s,  4, tw4);
            bfly(v, s,  2, tw2);
            float2 ox;
            ox.x = __shfl_xor_sync(0xffffffffu, v.x, 1);
            ox.y = __shfl_xor_sync(0xffffffffu, v.y, 1);
            v = (s & 1) ? make_float2(ox.x - v.x, ox.y - v.y)
                        : make_float2(v.x + ox.x, v.y + ox.y);
            float mv = mbase[(km * 7 + k1) * 32];
            v.x *= mv; v.y *= mv;
            ox.x = __shfl_xor_sync(0xffffffffu, v.x, 1);
            ox.y = __shfl_xor_sync(0xffffffffu, v.y, 1);
            v = (s & 1) ? csub(ox, v) : cadd(v, ox);
            ibfly(v, s,  2, tw2);
            ibfly(v, s,  4, tw4);
            ibfly(v, s,  8, tw8);
            ibfly(v, s, 16, tw16);
            vv[km] = v;                              // natural n index = s
        }
        float2 oc = cmulf(vv[1], make_float2(ws.x, -ws.y));
        z[k1][0] = cadd(vv[0], oc);
        z[k1][1] = csub(vv[0], oc);
    }

    // ---- final stage (inverse): chained conj twiddle + inverse radix-7 -> tile ----
    #pragma unroll
    for (int r = 0; r < 2; r++) {
        int n2 = 32 * r + s;
        float2 wstep = sW[n2]; wstep.y = -wstep.y;
        float2 cur = make_float2(1.f, 0.f);
        float2 y[7];
        #pragma unroll
        for (int k1 = 0; k1 < 7; k1++) {
            y[k1] = cmulf(z[k1][r], cur);
            cur = cmulf(cur, wstep);
        }
        float2 xo[7];
        dft7<true>(y, xo);
        #pragma unroll
        for (int n1 = 0; n1 < 7; n1++)
            tile[(n1 * 64 + n2) * TSTR8 + g] = xo[n1];   // this thread's own slots
    }
    __syncthreads();
    for (int i = 0; i < 14; i++) {
        int h = ls + 32 * i;
        gbase[h * Wd + w0 + lg] = tile[h * TSTR8 + lg];
    }
}

// -------- K3: DIT inverse row FFTs + conj-coil combine + q; partials qp (,rq, qq) --------
// 128-thread CTAs (4 warps, 1 row/warp) for finer wave granularity + higher residency.
__global__ __launch_bounds__(128) void k_rowfft_inv(const float* __restrict__ cr,
                                                    const float* __restrict__ ci,
                                                    const float* __restrict__ miu,
                                                    int it) {
    int last = (it == 4);
    __shared__ float2 sW[224];
    int tid = threadIdx.x;
    for (int i = tid; i < 224; i += 128) sW[i] = g_W224[i];
    __syncthreads();
    int warp = tid >> 5, t = tid & 31;
    float2 tw16 = sW[7  * (t & 15)];
    float2 tw8  = sW[14 * (t & 7)];
    float2 tw4  = sW[28 * (t & 3)];
    float2 tw2  = sW[56 * (t & 1)];
    int rid = blockIdx.x * 4 + warp;                 // < 5376 = D*H
    int h = rid % Hd;
    float2 accq[7];
    #pragma unroll
    for (int n1 = 0; n1 < 7; n1++) accq[n1] = make_float2(0.f, 0.f);
    float2 ynext[7];
    {
        const float2* srow = g_scr + (size_t)rid * Wd;
        #pragma unroll
        for (int k1 = 0; k1 < 7; k1++) ynext[k1] = srow[k1 * 32 + t];
    }
    for (int c = 0; c < Cd; c++) {
        float2 y[7];
        #pragma unroll
        for (int k1 = 0; k1 < 7; k1++) y[k1] = ynext[k1];
        if (c + 1 < Cd) {
            const float2* srow = g_scr + ((size_t)(c + 1) * DHW + (size_t)rid * Wd);
            #pragma unroll
            for (int k1 = 0; k1 < 7; k1++) ynext[k1] = srow[k1 * 32 + t];
        }
        const float* crr = cr + (c * Hd + h) * Wd;
        const float* cii = ci + (c * Hd + h) * Wd;
        float2 co[7];
        #pragma unroll
        for (int n1 = 0; n1 < 7; n1++) {
            int x = n1 * 32 + t;
            co[n1] = make_float2(crr[x], -cii[x]);
        }
        float2 xo[7];
        fft224_inv(sW, t, tw16, tw8, tw4, tw2, y, xo);
        #pragma unroll
        for (int n1 = 0; n1 < 7; n1++) cmadd(accq[n1], xo[n1], co[n1]);
    }
    float mu = fabsf(miu[0]);
    float2 qp = make_float2(0.f, 0.f);
    float2 rq = make_float2(0.f, 0.f);
    float qq = 0.f;
    const float2* prow = g_p + (size_t)rid * Wd;
    const float2* rrow = g_r + (size_t)rid * Wd;
    float2* qrow = g_q + (size_t)rid * Wd;
    if (!last) {
        #pragma unroll
        for (int n1 = 0; n1 < 7; n1++) {
            int x = n1 * 32 + t;
            float2 p = prow[x];
            float2 rv = (it == 0) ? p : rrow[x];     // r0 ≡ p0
            float2 q = make_float2(fmaf(mu, p.x, accq[n1].x), fmaf(mu, p.y, accq[n1].y));
            qrow[x] = q;
            qp.x += q.x * p.x + q.y * p.y;
            qp.y += q.y * p.x - q.x * p.y;
            rq.x += rv.x * q.x + rv.y * q.y;
            rq.y += rv.y * q.x - rv.x * q.y;
            qq = fmaf(q.x, q.x, fmaf(q.y, q.y, qq));
        }
    } else {
        #pragma unroll
        for (int n1 = 0; n1 < 7; n1++) {
            int x = n1 * 32 + t;
            float2 p = prow[x];
            float2 q = make_float2(fmaf(mu, p.x, accq[n1].x), fmaf(mu, p.y, accq[n1].y));
            qp.x += q.x * p.x + q.y * p.y;
            qp.y += q.y * p.x - q.x * p.y;
        }
    }
    qp = blockReduceC<4>(qp);
    if (!last) {
        rq = blockReduceC<4>(rq);
        qq = blockReduceF<4>(qq);
    }
    if (tid == 0) {
        g_qp_part[blockIdx.x] = qp;
        if (!last) {
            g_rq_part[blockIdx.x] = rq;
            g_qq_part[blockIdx.x] = qq;
        }
    }
}

// -------- fused: alpha + analytic rr_new + beta; b += al p; r -= al q; p = r + be p --------
// float4-vectorized. it==0 uses r ≡ p, b ≡ 0 (no r/b loads). Last iteration writes output.
__global__ __launch_bounds__(256) void k_update_br(int it, float* __restrict__ out) {
    __shared__ float2 s_al;
    __shared__ float s_be;
    int tid = threadIdx.x;
    float2 qp = make_float2(0.f, 0.f), rq = make_float2(0.f, 0.f);
    float qq = 0.f;
    if (it < 4) {
        for (int i = tid; i < NB_Q; i += 256) {
            qp.x += g_qp_part[i].x; qp.y += g_qp_part[i].y;
            rq.x += g_rq_part[i].x; rq.y += g_rq_part[i].y;
            qq += g_qq_part[i];
        }
        qp = blockReduceC<8>(qp);
        rq = blockReduceC<8>(rq);
        qq = blockReduceF<8>(qq);
    } else {
        for (int i = tid; i < NB_Q; i += 256) {
            qp.x += g_qp_part[i].x; qp.y += g_qp_part[i].y;
        }
        qp = blockReduceC<8>(qp);
    }
    float rr0 = 0.f;
    if (it == 0) {
        float v = 0.f;
        for (int i = tid; i < NB_EW; i += 256) v += g_rrp[i];
        rr0 = blockReduceF<8>(v);
    }
    if (tid == 0) {
        float rrv = (it == 0) ? rr0 : g_rr[it];
        float den = qp.x * qp.x + qp.y * qp.y;
        float2 al = make_float2(rrv * qp.x / den, -rrv * qp.y / den);
        s_al = al;
        if (it < 4) {
            float rr_new = rrv - 2.f * (al.x * rq.x + al.y * rq.y)
                         + (al.x * al.x + al.y * al.y) * qq;
            s_be = rr_new / rrv;
            if (blockIdx.x == 0) g_rr[it + 1] = rr_new;
        }
    }
    __syncthreads();
    float2 al = s_al;
    const float4* p4 = (const float4*)g_p;
    float4* b4 = (float4*)g_b;
    if (it < 4) {
        float be = s_be;
        const float4* q4 = (const float4*)g_q;
        float4* r4 = (float4*)g_r;
        float4* p4w = (float4*)g_p;
        for (int n = blockIdx.x * 256 + tid; n < DHW / 2; n += NB_EW * 256) {
            float4 p = p4[n], q = q4[n];
            float4 b, r;
            if (it == 0) {
                r = p;
                b = make_float4(0.f, 0.f, 0.f, 0.f);
            } else {
                r = r4[n];
                b = b4[n];
            }
            b.x += al.x * p.x - al.y * p.y;
            b.y += al.x * p.y + al.y * p.x;
            b.z += al.x * p.z - al.y * p.w;
            b.w += al.x * p.w + al.y * p.z;
            float r0x = r.x - (al.x * q.x - al.y * q.y);
            float r0y = r.y - (al.x * q.y + al.y * q.x);
            float r1x = r.z - (al.x * q.z - al.y * q.w);
            float r1y = r.w - (al.x * q.w + al.y * q.z);
            b4[n] = b;
            r4[n] = make_float4(r0x, r0y, r1x, r1y);
            p4w[n] = make_float4(fmaf(be, p.x, r0x), fmaf(be, p.y, r0y),
                                 fmaf(be, p.z, r1x), fmaf(be, p.w, r1y));
        }
    } else {
        float2* outr = (float2*)out;
        float2* outi = (float2*)(out + DHW);
        for (int n = blockIdx.x * 256 + tid; n < DHW / 2; n += NB_EW * 256) {
            float4 p = p4[n], b = b4[n];
            float b0x = b.x + al.x * p.x - al.y * p.y;
            float b0y = b.y + al.x * p.y + al.y * p.x;
            float b1x = b.z + al.x * p.z - al.y * p.w;
            float b1y = b.w + al.x * p.w + al.y * p.z;
            int n2 = 2 * n;
            int w = n2 % Wd;
            int h = (n2 / Wd) % Hd;
            float s0 = ((h + w) & 1) ? -1.f : 1.f;   // w+1 flips parity
            outr[n] = make_float2(s0 * b0x, -s0 * b1x);
            outi[n] = make_float2(s0 * b0y, -s0 * b1y);
        }
    }
}

extern "C" void kernel_launch(void* const* d_in, const int* in_sizes, int n_in,
                              void* d_out, int out_size) {
    const float* z    = (const float*)d_in[0];
    const float* zf   = (const float*)d_in[1];
    const float* cr   = (const float*)d_in[2];
    const float* ci   = (const float*)d_in[3];
    const int*   mask = (const int*)d_in[4];
    const float* miu  = (const float*)d_in[5];
    float* out = (float*)d_out;

    const int k2_shmem = 448 * TSTR8 * (int)sizeof(float2) + 448 * (int)sizeof(float2); // 35840
    cudaFuncSetAttribute(k_colfft, cudaFuncAttributeMaxDynamicSharedMemorySize, k2_shmem);

    k_setup<<<(HW + 255) / 256, 256>>>(mask);
    k_init<<<NB_EW, 256>>>(z, zf, miu);
    for (int it = 0; it < 5; ++it) {
        k_rowfft_fwd<<<6720, 256>>>(cr, ci);           // C*D*H/8
        k_colfft<<<3360, 256, k2_shmem>>>();           // C*D*(W/8)
        k_rowfft_inv<<<NB_Q, 128>>>(cr, ci, miu, it);  // D*H/4, 4 warps/CTA
        k_update_br<<<NB_EW, 256>>>(it, out);          // al (+rr_new, be); updates b,r,p / writes out
    }
}